// round 1
// baseline (speedup 1.0000x reference)
#include <cuda_runtime.h>
#include <math.h>

#define DM 1024
#define NH 16
#define DK 64
#define BB 4
#define TT 2048
#define MT (BB*TT)   // 8192 rows

// Scratch (static device arrays; allocation is forbidden)
__device__ float g_qp[(size_t)MT * DM];
__device__ float g_kp[(size_t)MT * DM];
__device__ float g_vp[(size_t)MT * DM];
__device__ float g_att[(size_t)MT * DM];

// ----------------------------------------------------------------------------
// SGEMM: Out[M,N] = X[M,K] @ W[N,K]^T + bias[N]   (torch-style weight layout)
// 128x128 tile, BK=16, 8x8 per thread, 256 threads.
// ----------------------------------------------------------------------------
__device__ __forceinline__ void sgemm_body(const float* __restrict__ X,
                                           const float* __restrict__ W,
                                           const float* __restrict__ bias,
                                           float* __restrict__ Out)
{
    const int K = DM, N = DM;
    __shared__ float As[16][132];   // [k][m], +4 pad
    __shared__ float Bs[16][132];   // [k][n]
    const int tid = threadIdx.x;
    const int tx = tid & 15, ty = tid >> 4;
    const int m0 = blockIdx.y * 128, n0 = blockIdx.x * 128;

    float acc[8][8];
#pragma unroll
    for (int i = 0; i < 8; i++)
#pragma unroll
        for (int j = 0; j < 8; j++) acc[i][j] = 0.f;

    for (int k0 = 0; k0 < K; k0 += 16) {
#pragma unroll
        for (int it = 0; it < 2; it++) {
            int idx = tid + it * 256;
            int r = idx >> 2, c4 = idx & 3;
            float4 a = *(const float4*)&X[(size_t)(m0 + r) * K + k0 + c4 * 4];
            As[c4 * 4 + 0][r] = a.x; As[c4 * 4 + 1][r] = a.y;
            As[c4 * 4 + 2][r] = a.z; As[c4 * 4 + 3][r] = a.w;
            float4 b = *(const float4*)&W[(size_t)(n0 + r) * K + k0 + c4 * 4];
            Bs[c4 * 4 + 0][r] = b.x; Bs[c4 * 4 + 1][r] = b.y;
            Bs[c4 * 4 + 2][r] = b.z; Bs[c4 * 4 + 3][r] = b.w;
        }
        __syncthreads();
#pragma unroll
        for (int k = 0; k < 16; k++) {
            float a[8], b[8];
            *(float4*)&a[0] = *(const float4*)&As[k][ty * 8];
            *(float4*)&a[4] = *(const float4*)&As[k][ty * 8 + 4];
            *(float4*)&b[0] = *(const float4*)&Bs[k][tx * 8];
            *(float4*)&b[4] = *(const float4*)&Bs[k][tx * 8 + 4];
#pragma unroll
            for (int i = 0; i < 8; i++)
#pragma unroll
                for (int j = 0; j < 8; j++) acc[i][j] += a[i] * b[j];
        }
        __syncthreads();
    }

#pragma unroll
    for (int i = 0; i < 8; i++) {
        int row = m0 + ty * 8 + i;
#pragma unroll
        for (int j4 = 0; j4 < 2; j4++) {
            int col = n0 + tx * 8 + j4 * 4;
            float4 bv = *(const float4*)&bias[col];
            float4 r;
            r.x = acc[i][j4 * 4 + 0] + bv.x;
            r.y = acc[i][j4 * 4 + 1] + bv.y;
            r.z = acc[i][j4 * 4 + 2] + bv.z;
            r.w = acc[i][j4 * 4 + 3] + bv.w;
            *(float4*)&Out[(size_t)row * N + col] = r;
        }
    }
}

__global__ __launch_bounds__(256) void qkv_kernel(const float* __restrict__ X,
    const float* __restrict__ Wq, const float* __restrict__ bq,
    const float* __restrict__ Wk, const float* __restrict__ bk,
    const float* __restrict__ Wv, const float* __restrict__ bv)
{
    const float* W = (blockIdx.z == 0) ? Wq : (blockIdx.z == 1) ? Wk : Wv;
    const float* bb = (blockIdx.z == 0) ? bq : (blockIdx.z == 1) ? bk : bv;
    float* O = (blockIdx.z == 0) ? g_qp : (blockIdx.z == 1) ? g_kp : g_vp;
    sgemm_body(X, W, bb, O);
}

__global__ __launch_bounds__(256) void oproj_kernel(const float* __restrict__ Wo,
                                                    const float* __restrict__ bo,
                                                    float* __restrict__ Out)
{
    sgemm_body(g_att, Wo, bo, Out);
}

// ----------------------------------------------------------------------------
// Flash attention, fp32, causal. One block per (q-tile 64, batch*head).
// 256 threads = 16x16, each owns a 4x4 fragment of the 64x64 S/P/O tiles.
// smem: Qs[d][q] (transposed), KPs[d][k] (K, reused as P[r][c]), Vs[k][d].
// ----------------------------------------------------------------------------
#define ALD 68
#define ATTN_SMEM (3 * 64 * ALD * 4)

__global__ __launch_bounds__(256) void attn_kernel()
{
    extern __shared__ float sm[];
    float* Qs  = sm;                 // [64][ALD]  layout [kk][r]
    float* KPs = sm + 64 * ALD;      // [64][ALD]  K: [kk][c], then P: [r][c]
    float* Vs  = sm + 2 * 64 * ALD;  // [64][ALD]  [c][d]

    const int qt = blockIdx.x, bh = blockIdx.y;
    const int b = bh >> 4, h = bh & 15;
    const int tid = threadIdx.x, tx = tid & 15, ty = tid >> 4;
    const size_t base = ((size_t)b * TT) * DM + (size_t)h * DK;
    const int q0 = qt * 64;

    // Load Q tile transposed: Qs[kk][r]
    const float* Qg = g_qp + base + (size_t)q0 * DM;
#pragma unroll
    for (int it = 0; it < 4; it++) {
        int idx = tid + it * 256;
        int r = idx >> 4, c4 = idx & 15;
        float4 v = *(const float4*)&Qg[(size_t)r * DM + c4 * 4];
        Qs[(c4 * 4 + 0) * ALD + r] = v.x;
        Qs[(c4 * 4 + 1) * ALD + r] = v.y;
        Qs[(c4 * 4 + 2) * ALD + r] = v.z;
        Qs[(c4 * 4 + 3) * ALD + r] = v.w;
    }

    float o[4][4];
    float mi[4], li[4];
#pragma unroll
    for (int i = 0; i < 4; i++) {
        mi[i] = -INFINITY; li[i] = 0.f;
#pragma unroll
        for (int j = 0; j < 4; j++) o[i][j] = 0.f;
    }

    for (int jt = 0; jt <= qt; jt++) {
        __syncthreads();   // previous PV done before overwriting KPs/Vs
        const float* Kg = g_kp + base + (size_t)jt * 64 * DM;
        const float* Vg = g_vp + base + (size_t)jt * 64 * DM;
#pragma unroll
        for (int it = 0; it < 4; it++) {
            int idx = tid + it * 256;
            int r = idx >> 4, c4 = idx & 15;
            float4 v = *(const float4*)&Kg[(size_t)r * DM + c4 * 4];
            KPs[(c4 * 4 + 0) * ALD + r] = v.x;
            KPs[(c4 * 4 + 1) * ALD + r] = v.y;
            KPs[(c4 * 4 + 2) * ALD + r] = v.z;
            KPs[(c4 * 4 + 3) * ALD + r] = v.w;
            float4 w = *(const float4*)&Vg[(size_t)r * DM + c4 * 4];
            *(float4*)&Vs[r * ALD + c4 * 4] = w;
        }
        __syncthreads();

        // S = Q K^T  (64x64x64)
        float s[4][4];
#pragma unroll
        for (int i = 0; i < 4; i++)
#pragma unroll
            for (int j = 0; j < 4; j++) s[i][j] = 0.f;
#pragma unroll 8
        for (int kk = 0; kk < 64; kk++) {
            float4 qv = *(const float4*)&Qs[kk * ALD + 4 * ty];
            float4 kv = *(const float4*)&KPs[kk * ALD + 4 * tx];
            float a[4] = {qv.x, qv.y, qv.z, qv.w};
            float c[4] = {kv.x, kv.y, kv.z, kv.w};
#pragma unroll
            for (int i = 0; i < 4; i++)
#pragma unroll
                for (int j = 0; j < 4; j++) s[i][j] += a[i] * c[j];
        }

        const float sc = 0.125f;  // 1/sqrt(64)
        if (jt == qt) {
#pragma unroll
            for (int i = 0; i < 4; i++)
#pragma unroll
                for (int j = 0; j < 4; j++) {
                    int gq = q0 + 4 * ty + i;
                    int gk = jt * 64 + 4 * tx + j;
                    s[i][j] = (gk > gq) ? -INFINITY : s[i][j] * sc;
                }
        } else {
#pragma unroll
            for (int i = 0; i < 4; i++)
#pragma unroll
                for (int j = 0; j < 4; j++) s[i][j] *= sc;
        }

        // online softmax per row (reduce across the 16 tx lanes)
#pragma unroll
        for (int i = 0; i < 4; i++) {
            float mx = fmaxf(fmaxf(s[i][0], s[i][1]), fmaxf(s[i][2], s[i][3]));
#pragma unroll
            for (int off = 8; off; off >>= 1)
                mx = fmaxf(mx, __shfl_xor_sync(0xffffffffu, mx, off, 32));
            float mnew = fmaxf(mi[i], mx);
            float corr = __expf(mi[i] - mnew);
            float rs = 0.f;
#pragma unroll
            for (int j = 0; j < 4; j++) {
                float p = __expf(s[i][j] - mnew);
                s[i][j] = p; rs += p;
            }
#pragma unroll
            for (int off = 8; off; off >>= 1)
                rs += __shfl_xor_sync(0xffffffffu, rs, off, 32);
            li[i] = li[i] * corr + rs;
            mi[i] = mnew;
#pragma unroll
            for (int j = 0; j < 4; j++) o[i][j] *= corr;
        }

        __syncthreads();   // all reads of K done before P overwrites KPs
#pragma unroll
        for (int i = 0; i < 4; i++)
            *(float4*)&KPs[(4 * ty + i) * ALD + 4 * tx] =
                make_float4(s[i][0], s[i][1], s[i][2], s[i][3]);
        __syncthreads();

        // O += P V   (64x64x64)
#pragma unroll 8
        for (int c = 0; c < 64; c++) {
            float4 vv = *(const float4*)&Vs[c * ALD + 4 * tx];
            float vr[4] = {vv.x, vv.y, vv.z, vv.w};
            float pr[4];
#pragma unroll
            for (int i = 0; i < 4; i++) pr[i] = KPs[(4 * ty + i) * ALD + c];
#pragma unroll
            for (int i = 0; i < 4; i++)
#pragma unroll
                for (int j = 0; j < 4; j++) o[i][j] += pr[i] * vr[j];
        }
    }

    // finalize: O / l, write to g_att
    float* Og = g_att + base + (size_t)q0 * DM;
#pragma unroll
    for (int i = 0; i < 4; i++) {
        float inv = 1.f / li[i];
        float4 r = make_float4(o[i][0] * inv, o[i][1] * inv,
                               o[i][2] * inv, o[i][3] * inv);
        *(float4*)&Og[(size_t)(4 * ty + i) * DM + 4 * tx] = r;
    }
}

// ----------------------------------------------------------------------------
extern "C" void kernel_launch(void* const* d_in, const int* in_sizes, int n_in,
                              void* d_out, int out_size)
{
    const float* q  = (const float*)d_in[0];
    // d_in[1] = mask (causal, known at compile time) — unused
    const float* Wq = (const float*)d_in[2];
    const float* bq = (const float*)d_in[3];
    const float* Wk = (const float*)d_in[4];
    const float* bk = (const float*)d_in[5];
    const float* Wv = (const float*)d_in[6];
    const float* bv = (const float*)d_in[7];
    const float* Wo = (const float*)d_in[8];
    const float* bo = (const float*)d_in[9];
    float* out = (float*)d_out;

    // QKV projections: one launch, z picks the weight/output
    dim3 gq(DM / 128, MT / 128, 3);
    qkv_kernel<<<gq, 256>>>(q, Wq, bq, Wk, bk, Wv, bv);

    // Flash attention
    cudaFuncSetAttribute(attn_kernel,
                         cudaFuncAttributeMaxDynamicSharedMemorySize, ATTN_SMEM);
    dim3 ga(TT / 64, BB * NH);
    attn_kernel<<<ga, 256, ATTN_SMEM>>>();

    // Output projection
    dim3 go(DM / 128, MT / 128, 1);
    oproj_kernel<<<go, 256>>>(Wo, bo, out);
}

// round 4
// speedup vs baseline: 1.4409x; 1.4409x over previous
#include <cuda_runtime.h>
#include <cuda_bf16.h>
#include <math.h>
#include <stdint.h>

#define DM 1024
#define NH 16
#define DK 64
#define BB 4
#define TT 2048
#define MT (BB*TT)   // 8192 rows

// ---------------- scratch (static; allocation forbidden) ----------------
__device__ float g_qp[(size_t)MT * DM];
__device__ float g_kp[(size_t)MT * DM];
__device__ float g_vp[(size_t)MT * DM];
__device__ float g_att[(size_t)MT * DM];
__device__ __nv_bfloat16 g_xhi[(size_t)MT * DM];
__device__ __nv_bfloat16 g_xlo[(size_t)MT * DM];
__device__ __nv_bfloat16 g_ahi[(size_t)MT * DM];
__device__ __nv_bfloat16 g_alo[(size_t)MT * DM];
__device__ __nv_bfloat16 g_whi[(size_t)4 * DM * DM];
__device__ __nv_bfloat16 g_wlo[(size_t)4 * DM * DM];

// ---------------- helpers ----------------
__device__ __forceinline__ uint32_t smem_u32(const void* p) {
    uint32_t a;
    asm("{ .reg .u64 t; cvta.to.shared.u64 t, %1; cvt.u32.u64 %0, t; }" : "=r"(a) : "l"(p));
    return a;
}
__device__ __forceinline__ void cp16(uint32_t dst, const void* src) {
    asm volatile("cp.async.cg.shared.global [%0], [%1], 16;" :: "r"(dst), "l"(src));
}
__device__ __forceinline__ void ldsm4(uint32_t* r, uint32_t addr) {
    asm volatile("ldmatrix.sync.aligned.m8n8.x4.shared.b16 {%0,%1,%2,%3}, [%4];"
                 : "=r"(r[0]), "=r"(r[1]), "=r"(r[2]), "=r"(r[3]) : "r"(addr));
}
__device__ __forceinline__ void mma16816(float* c, const uint32_t* a, const uint32_t* b) {
    asm volatile("mma.sync.aligned.m16n8k16.row.col.f32.bf16.bf16.f32 "
                 "{%0,%1,%2,%3}, {%4,%5,%6,%7}, {%8,%9}, {%0,%1,%2,%3};"
                 : "+f"(c[0]), "+f"(c[1]), "+f"(c[2]), "+f"(c[3])
                 : "r"(a[0]), "r"(a[1]), "r"(a[2]), "r"(a[3]), "r"(b[0]), "r"(b[1]));
}

// ---------------- fp32 -> bf16 hi/lo split ----------------
__global__ __launch_bounds__(256) void cvt_kernel(const float* __restrict__ x,
                                                  __nv_bfloat16* __restrict__ hi,
                                                  __nv_bfloat16* __restrict__ lo, int n4)
{
    int i = blockIdx.x * 256 + threadIdx.x;
    if (i >= n4) return;
    float4 v = ((const float4*)x)[i];
    __nv_bfloat16 h0 = __float2bfloat16(v.x);
    __nv_bfloat16 h1 = __float2bfloat16(v.y);
    __nv_bfloat16 h2 = __float2bfloat16(v.z);
    __nv_bfloat16 h3 = __float2bfloat16(v.w);
    __nv_bfloat16 l0 = __float2bfloat16(v.x - __bfloat162float(h0));
    __nv_bfloat16 l1 = __float2bfloat16(v.y - __bfloat162float(h1));
    __nv_bfloat16 l2 = __float2bfloat16(v.z - __bfloat162float(h2));
    __nv_bfloat16 l3 = __float2bfloat16(v.w - __bfloat162float(h3));
    __nv_bfloat162* hp = (__nv_bfloat162*)(hi + (size_t)i * 4);
    __nv_bfloat162* lp = (__nv_bfloat162*)(lo + (size_t)i * 4);
    hp[0] = __nv_bfloat162(h0, h1); hp[1] = __nv_bfloat162(h2, h3);
    lp[0] = __nv_bfloat162(l0, l1); lp[1] = __nv_bfloat162(l2, l3);
}

// ---------------- mma.sync GEMM: Out[M,N] = A[M,K] @ W[N,K]^T + bias ----------------
// 128x128 CTA tile, 8 warps (2x4), warp tile 64x32, BK=32 bf16, double-buffered
// cp.async. Hi/lo split: acc += Ahi*Bhi + Ahi*Blo + Alo*Bhi (single fp32 acc).
#define BKc 32
#define BKP 40                     // padded smem stride (elements) -> conflict-free ldmatrix
#define MAT_B (128 * BKP * 2)      // 10240 bytes per matrix tile
#define STAGE_B (4 * MAT_B)        // Ahi, Alo, Bhi, Blo
#define GEMM_SMEM (2 * STAGE_B)    // 81920
#define NKCH (DM / BKc)            // 32

__device__ __forceinline__ void gemm_mma_body(
    const __nv_bfloat16* __restrict__ Ahi, const __nv_bfloat16* __restrict__ Alo,
    const __nv_bfloat16* __restrict__ Bhi, const __nv_bfloat16* __restrict__ Blo,
    const float* __restrict__ bias, float* __restrict__ Out)
{
    extern __shared__ char smc[];
    const uint32_t sb = smem_u32(smc);
    const int tid = threadIdx.x, wid = tid >> 5, lane = tid & 31;
    const int warp_m = wid >> 2, warp_n = wid & 3;       // 2 x 4
    const int m0 = blockIdx.y * 128, n0 = blockIdx.x * 128;

    float acc[4][4][4];
#pragma unroll
    for (int i = 0; i < 4; i++)
#pragma unroll
        for (int j = 0; j < 4; j++)
#pragma unroll
            for (int k = 0; k < 4; k++) acc[i][j][k] = 0.f;

    // stage loader: 4 matrices x 128 rows x 4 16B-segments
    auto load_stage = [&](int c, int st) {
        const uint32_t sbase = sb + st * STAGE_B;
        const int k0 = c * BKc;
#pragma unroll
        for (int t = 0; t < 8; t++) {
            const int mat = t >> 1;
            const int rem = ((t & 1) << 8) + tid;
            const int row = rem >> 2, seg = rem & 3;
            const uint32_t dst = sbase + mat * MAT_B + row * (BKP * 2) + seg * 16;
            const __nv_bfloat16* src;
            if      (mat == 0) src = Ahi + (size_t)(m0 + row) * DM + k0 + seg * 8;
            else if (mat == 1) src = Alo + (size_t)(m0 + row) * DM + k0 + seg * 8;
            else if (mat == 2) src = Bhi + (size_t)(n0 + row) * DM + k0 + seg * 8;
            else               src = Blo + (size_t)(n0 + row) * DM + k0 + seg * 8;
            cp16(dst, src);
        }
        asm volatile("cp.async.commit_group;");
    };

    load_stage(0, 0);

    for (int c = 0; c < NKCH; c++) {
        if (c + 1 < NKCH) {
            load_stage(c + 1, (c + 1) & 1);
            asm volatile("cp.async.wait_group 1;" ::: "memory");
        } else {
            asm volatile("cp.async.wait_group 0;" ::: "memory");
        }
        __syncthreads();

        const uint32_t sbase = sb + (c & 1) * STAGE_B;
        const uint32_t aHi = sbase;
        const uint32_t aLo = sbase + MAT_B;
        const uint32_t bHi = sbase + 2 * MAT_B;
        const uint32_t bLo = sbase + 3 * MAT_B;

        // lane addressing
        const int arow = warp_m * 64 + (lane & 15);
        const int aseg = (lane >> 4) * 8;
        const int bn   = warp_n * 32 + ((lane >> 4) * 8) + (lane & 7);
        const int bk   = ((lane >> 3) & 1) * 8;

#pragma unroll
        for (int ks = 0; ks < 2; ks++) {
            const int k0 = ks * 16;
            uint32_t ah[4][4], al[4][4];
#pragma unroll
            for (int mt = 0; mt < 4; mt++) {
                uint32_t off = ((arow + mt * 16) * BKP + k0 + aseg) * 2;
                ldsm4(ah[mt], aHi + off);
                ldsm4(al[mt], aLo + off);
            }
            uint32_t bh[2][4], bl[2][4];
#pragma unroll
            for (int np = 0; np < 2; np++) {
                uint32_t off = ((bn + np * 16) * BKP + k0 + bk) * 2;
                ldsm4(bh[np], bHi + off);
                ldsm4(bl[np], bLo + off);
            }
#pragma unroll
            for (int mt = 0; mt < 4; mt++)
#pragma unroll
                for (int nt = 0; nt < 4; nt++) {
                    const uint32_t* Bh = &bh[nt >> 1][(nt & 1) * 2];
                    const uint32_t* Bl = &bl[nt >> 1][(nt & 1) * 2];
                    mma16816(acc[mt][nt], ah[mt], Bh);
                    mma16816(acc[mt][nt], ah[mt], Bl);
                    mma16816(acc[mt][nt], al[mt], Bh);
                }
        }
        __syncthreads();
    }

    // epilogue: c0,c1 -> (row, col..col+1); c2,c3 -> (row+8, col..col+1)
    const int rbase = m0 + warp_m * 64 + (lane >> 2);
    const int cbase = n0 + warp_n * 32 + (lane & 3) * 2;
#pragma unroll
    for (int mt = 0; mt < 4; mt++) {
#pragma unroll
        for (int nt = 0; nt < 4; nt++) {
            const int col = cbase + nt * 8;
            const float b0 = bias[col], b1 = bias[col + 1];
            float* p0 = Out + (size_t)(rbase + mt * 16) * DM + col;
            float* p1 = Out + (size_t)(rbase + mt * 16 + 8) * DM + col;
            p0[0] = acc[mt][nt][0] + b0; p0[1] = acc[mt][nt][1] + b1;
            p1[0] = acc[mt][nt][2] + b0; p1[1] = acc[mt][nt][3] + b1;
        }
    }
}

__global__ __launch_bounds__(256, 1) void qkv_mma_kernel(
    const float* __restrict__ bq, const float* __restrict__ bk, const float* __restrict__ bv)
{
    const size_t wo = (size_t)blockIdx.z * DM * DM;
    const float* bias = (blockIdx.z == 0) ? bq : (blockIdx.z == 1) ? bk : bv;
    float* Out = (blockIdx.z == 0) ? g_qp : (blockIdx.z == 1) ? g_kp : g_vp;
    gemm_mma_body(g_xhi, g_xlo, g_whi + wo, g_wlo + wo, bias, Out);
}

__global__ __launch_bounds__(256, 1) void oproj_mma_kernel(const float* __restrict__ bo,
                                                           float* __restrict__ Out)
{
    const size_t wo = (size_t)3 * DM * DM;
    gemm_mma_body(g_ahi, g_alo, g_whi + wo, g_wlo + wo, bo, Out);
}

// ---------------- flash attention (fp32, same as R1) ----------------
#define ALD 68
#define ATTN_SMEM (3 * 64 * ALD * 4)

__global__ __launch_bounds__(256) void attn_kernel()
{
    extern __shared__ float smf[];
    float* Qs  = smf;
    float* KPs = smf + 64 * ALD;
    float* Vs  = smf + 2 * 64 * ALD;

    const int qt = blockIdx.x, bh = blockIdx.y;
    const int b = bh >> 4, h = bh & 15;
    const int tid = threadIdx.x, tx = tid & 15, ty = tid >> 4;
    const size_t base = ((size_t)b * TT) * DM + (size_t)h * DK;
    const int q0 = qt * 64;

    const float* Qg = g_qp + base + (size_t)q0 * DM;
#pragma unroll
    for (int it = 0; it < 4; it++) {
        int idx = tid + it * 256;
        int r = idx >> 4, c4 = idx & 15;
        float4 v = *(const float4*)&Qg[(size_t)r * DM + c4 * 4];
        Qs[(c4 * 4 + 0) * ALD + r] = v.x;
        Qs[(c4 * 4 + 1) * ALD + r] = v.y;
        Qs[(c4 * 4 + 2) * ALD + r] = v.z;
        Qs[(c4 * 4 + 3) * ALD + r] = v.w;
    }

    float o[4][4], mi[4], li[4];
#pragma unroll
    for (int i = 0; i < 4; i++) {
        mi[i] = -INFINITY; li[i] = 0.f;
#pragma unroll
        for (int j = 0; j < 4; j++) o[i][j] = 0.f;
    }

    for (int jt = 0; jt <= qt; jt++) {
        __syncthreads();
        const float* Kg = g_kp + base + (size_t)jt * 64 * DM;
        const float* Vg = g_vp + base + (size_t)jt * 64 * DM;
#pragma unroll
        for (int it = 0; it < 4; it++) {
            int idx = tid + it * 256;
            int r = idx >> 4, c4 = idx & 15;
            float4 v = *(const float4*)&Kg[(size_t)r * DM + c4 * 4];
            KPs[(c4 * 4 + 0) * ALD + r] = v.x;
            KPs[(c4 * 4 + 1) * ALD + r] = v.y;
            KPs[(c4 * 4 + 2) * ALD + r] = v.z;
            KPs[(c4 * 4 + 3) * ALD + r] = v.w;
            float4 w = *(const float4*)&Vg[(size_t)r * DM + c4 * 4];
            *(float4*)&Vs[r * ALD + c4 * 4] = w;
        }
        __syncthreads();

        float s[4][4];
#pragma unroll
        for (int i = 0; i < 4; i++)
#pragma unroll
            for (int j = 0; j < 4; j++) s[i][j] = 0.f;
#pragma unroll 8
        for (int kk = 0; kk < 64; kk++) {
            float4 qv = *(const float4*)&Qs[kk * ALD + 4 * ty];
            float4 kv = *(const float4*)&KPs[kk * ALD + 4 * tx];
            float a[4] = {qv.x, qv.y, qv.z, qv.w};
            float c[4] = {kv.x, kv.y, kv.z, kv.w};
#pragma unroll
            for (int i = 0; i < 4; i++)
#pragma unroll
                for (int j = 0; j < 4; j++) s[i][j] += a[i] * c[j];
        }

        const float sc = 0.125f;
        if (jt == qt) {
#pragma unroll
            for (int i = 0; i < 4; i++)
#pragma unroll
                for (int j = 0; j < 4; j++) {
                    int gq = q0 + 4 * ty + i;
                    int gk = jt * 64 + 4 * tx + j;
                    s[i][j] = (gk > gq) ? -INFINITY : s[i][j] * sc;
                }
        } else {
#pragma unroll
            for (int i = 0; i < 4; i++)
#pragma unroll
                for (int j = 0; j < 4; j++) s[i][j] *= sc;
        }

#pragma unroll
        for (int i = 0; i < 4; i++) {
            float mx = fmaxf(fmaxf(s[i][0], s[i][1]), fmaxf(s[i][2], s[i][3]));
#pragma unroll
            for (int off = 8; off; off >>= 1)
                mx = fmaxf(mx, __shfl_xor_sync(0xffffffffu, mx, off, 32));
            float mnew = fmaxf(mi[i], mx);
            float corr = __expf(mi[i] - mnew);
            float rs = 0.f;
#pragma unroll
            for (int j = 0; j < 4; j++) {
                float p = __expf(s[i][j] - mnew);
                s[i][j] = p; rs += p;
            }
#pragma unroll
            for (int off = 8; off; off >>= 1)
                rs += __shfl_xor_sync(0xffffffffu, rs, off, 32);
            li[i] = li[i] * corr + rs;
            mi[i] = mnew;
#pragma unroll
            for (int j = 0; j < 4; j++) o[i][j] *= corr;
        }

        __syncthreads();
#pragma unroll
        for (int i = 0; i < 4; i++)
            *(float4*)&KPs[(4 * ty + i) * ALD + 4 * tx] =
                make_float4(s[i][0], s[i][1], s[i][2], s[i][3]);
        __syncthreads();

#pragma unroll 8
        for (int c = 0; c < 64; c++) {
            float4 vv = *(const float4*)&Vs[c * ALD + 4 * tx];
            float vr[4] = {vv.x, vv.y, vv.z, vv.w};
            float pr[4];
#pragma unroll
            for (int i = 0; i < 4; i++) pr[i] = KPs[(4 * ty + i) * ALD + c];
#pragma unroll
            for (int i = 0; i < 4; i++)
#pragma unroll
                for (int j = 0; j < 4; j++) o[i][j] += pr[i] * vr[j];
        }
    }

    float* Og = g_att + base + (size_t)q0 * DM;
#pragma unroll
    for (int i = 0; i < 4; i++) {
        float inv = 1.f / li[i];
        float4 r = make_float4(o[i][0] * inv, o[i][1] * inv,
                               o[i][2] * inv, o[i][3] * inv);
        *(float4*)&Og[(size_t)(4 * ty + i) * DM + 4 * tx] = r;
    }
}

// ----------------------------------------------------------------------------
extern "C" void kernel_launch(void* const* d_in, const int* in_sizes, int n_in,
                              void* d_out, int out_size)
{
    const float* q  = (const float*)d_in[0];
    const float* Wq = (const float*)d_in[2];
    const float* bq = (const float*)d_in[3];
    const float* Wk = (const float*)d_in[4];
    const float* bk = (const float*)d_in[5];
    const float* Wv = (const float*)d_in[6];
    const float* bv = (const float*)d_in[7];
    const float* Wo = (const float*)d_in[8];
    const float* bo = (const float*)d_in[9];
    float* out = (float*)d_out;

    cudaFuncSetAttribute(qkv_mma_kernel, cudaFuncAttributeMaxDynamicSharedMemorySize, GEMM_SMEM);
    cudaFuncSetAttribute(oproj_mma_kernel, cudaFuncAttributeMaxDynamicSharedMemorySize, GEMM_SMEM);
    cudaFuncSetAttribute(attn_kernel, cudaFuncAttributeMaxDynamicSharedMemorySize, ATTN_SMEM);

    __nv_bfloat16 *whi, *wlo, *xhi, *xlo, *ahi, *alo;
    cudaGetSymbolAddress((void**)&whi, g_whi);
    cudaGetSymbolAddress((void**)&wlo, g_wlo);
    cudaGetSymbolAddress((void**)&xhi, g_xhi);
    cudaGetSymbolAddress((void**)&xlo, g_xlo);
    cudaGetSymbolAddress((void**)&ahi, g_ahi);
    cudaGetSymbolAddress((void**)&alo, g_alo);
    float* gatt;
    cudaGetSymbolAddress((void**)&gatt, g_att);

    const int nX4 = MT * DM / 4, nW4 = DM * DM / 4;
    cvt_kernel<<<(nX4 + 255) / 256, 256>>>(q, xhi, xlo, nX4);
    cvt_kernel<<<(nW4 + 255) / 256, 256>>>(Wq, whi, wlo, nW4);
    cvt_kernel<<<(nW4 + 255) / 256, 256>>>(Wk, whi + (size_t)DM * DM, wlo + (size_t)DM * DM, nW4);
    cvt_kernel<<<(nW4 + 255) / 256, 256>>>(Wv, whi + (size_t)2 * DM * DM, wlo + (size_t)2 * DM * DM, nW4);
    cvt_kernel<<<(nW4 + 255) / 256, 256>>>(Wo, whi + (size_t)3 * DM * DM, wlo + (size_t)3 * DM * DM, nW4);

    dim3 gq(DM / 128, MT / 128, 3);
    qkv_mma_kernel<<<gq, 256, GEMM_SMEM>>>(bq, bk, bv);

    dim3 ga(TT / 64, BB * NH);
    attn_kernel<<<ga, 256, ATTN_SMEM>>>();

    cvt_kernel<<<(nX4 + 255) / 256, 256>>>(gatt, ahi, alo, nX4);

    dim3 go(DM / 128, MT / 128, 1);
    oproj_mma_kernel<<<go, 256, GEMM_SMEM>>>(bo, out);
}

// round 5
// speedup vs baseline: 2.5463x; 1.7672x over previous
#include <cuda_runtime.h>
#include <cuda_bf16.h>
#include <math.h>
#include <stdint.h>

#define DM 1024
#define NH 16
#define DK 64
#define BB 4
#define TT 2048
#define MT (BB*TT)   // 8192 rows

// ---------------- scratch (static; allocation forbidden) ----------------
__device__ __nv_bfloat16 g_xhi[(size_t)MT * DM];
__device__ __nv_bfloat16 g_xlo[(size_t)MT * DM];
__device__ __nv_bfloat16 g_qhi[(size_t)MT * DM];
__device__ __nv_bfloat16 g_qlo[(size_t)MT * DM];
__device__ __nv_bfloat16 g_khi[(size_t)MT * DM];
__device__ __nv_bfloat16 g_klo[(size_t)MT * DM];
__device__ __nv_bfloat16 g_vhi[(size_t)MT * DM];
__device__ __nv_bfloat16 g_vlo[(size_t)MT * DM];
__device__ __nv_bfloat16 g_ahi[(size_t)MT * DM];
__device__ __nv_bfloat16 g_alo[(size_t)MT * DM];
__device__ __nv_bfloat16 g_whi[(size_t)4 * DM * DM];
__device__ __nv_bfloat16 g_wlo[(size_t)4 * DM * DM];

// ---------------- helpers ----------------
__device__ __forceinline__ uint32_t smem_u32(const void* p) {
    uint32_t a;
    asm("{ .reg .u64 t; cvta.to.shared.u64 t, %1; cvt.u32.u64 %0, t; }" : "=r"(a) : "l"(p));
    return a;
}
__device__ __forceinline__ void cp16(uint32_t dst, const void* src) {
    asm volatile("cp.async.cg.shared.global [%0], [%1], 16;" :: "r"(dst), "l"(src));
}
__device__ __forceinline__ void ldsm4(uint32_t* r, uint32_t addr) {
    asm volatile("ldmatrix.sync.aligned.m8n8.x4.shared.b16 {%0,%1,%2,%3}, [%4];"
                 : "=r"(r[0]), "=r"(r[1]), "=r"(r[2]), "=r"(r[3]) : "r"(addr));
}
__device__ __forceinline__ void ldsm4t(uint32_t* r, uint32_t addr) {
    asm volatile("ldmatrix.sync.aligned.m8n8.x4.trans.shared.b16 {%0,%1,%2,%3}, [%4];"
                 : "=r"(r[0]), "=r"(r[1]), "=r"(r[2]), "=r"(r[3]) : "r"(addr));
}
__device__ __forceinline__ void mma16816(float* c, const uint32_t* a, const uint32_t* b) {
    asm volatile("mma.sync.aligned.m16n8k16.row.col.f32.bf16.bf16.f32 "
                 "{%0,%1,%2,%3}, {%4,%5,%6,%7}, {%8,%9}, {%0,%1,%2,%3};"
                 : "+f"(c[0]), "+f"(c[1]), "+f"(c[2]), "+f"(c[3])
                 : "r"(a[0]), "r"(a[1]), "r"(a[2]), "r"(a[3]), "r"(b[0]), "r"(b[1]));
}
__device__ __forceinline__ uint32_t pack_bf2(float x, float y) {
    __nv_bfloat162 t = __floats2bfloat162_rn(x, y);   // low = x
    return *(uint32_t*)&t;
}
__device__ __forceinline__ void split_pair(float x, float y, uint32_t& hi, uint32_t& lo) {
    hi = pack_bf2(x, y);
    __nv_bfloat162 hv = *(__nv_bfloat162*)&hi;
    lo = pack_bf2(x - __bfloat162float(hv.x), y - __bfloat162float(hv.y));
}

// ---------------- fp32 -> bf16 hi/lo split ----------------
__global__ __launch_bounds__(256) void cvt_kernel(const float* __restrict__ x,
                                                  __nv_bfloat16* __restrict__ hi,
                                                  __nv_bfloat16* __restrict__ lo, int n4)
{
    int i = blockIdx.x * 256 + threadIdx.x;
    if (i >= n4) return;
    float4 v = ((const float4*)x)[i];
    uint32_t h0, l0, h1, l1;
    split_pair(v.x, v.y, h0, l0);
    split_pair(v.z, v.w, h1, l1);
    uint32_t* hp = (uint32_t*)(hi + (size_t)i * 4);
    uint32_t* lp = (uint32_t*)(lo + (size_t)i * 4);
    hp[0] = h0; hp[1] = h1;
    lp[0] = l0; lp[1] = l1;
}

// ---------------- mma.sync GEMM: Out[M,N] = A[M,K] @ W[N,K]^T + bias ----------------
#define BKc 32
#define BKP 40
#define MAT_B (128 * BKP * 2)
#define STAGE_B (4 * MAT_B)
#define GEMM_SMEM (2 * STAGE_B)    // 81920
#define NKCH (DM / BKc)            // 32

// OUTMODE 0: fp32 out. OUTMODE 1: bf16 hi/lo out, scaled.
template<int OUTMODE>
__device__ __forceinline__ void gemm_mma_body(
    const __nv_bfloat16* __restrict__ Ahi, const __nv_bfloat16* __restrict__ Alo,
    const __nv_bfloat16* __restrict__ Bhi, const __nv_bfloat16* __restrict__ Blo,
    const float* __restrict__ bias, float* __restrict__ OutF,
    __nv_bfloat16* __restrict__ Ohi, __nv_bfloat16* __restrict__ Olo, float scale)
{
    extern __shared__ char smc[];
    const uint32_t sb = smem_u32(smc);
    const int tid = threadIdx.x, wid = tid >> 5, lane = tid & 31;
    const int warp_m = wid >> 2, warp_n = wid & 3;
    const int m0 = blockIdx.y * 128, n0 = blockIdx.x * 128;

    float acc[4][4][4];
#pragma unroll
    for (int i = 0; i < 4; i++)
#pragma unroll
        for (int j = 0; j < 4; j++)
#pragma unroll
            for (int k = 0; k < 4; k++) acc[i][j][k] = 0.f;

    auto load_stage = [&](int c, int st) {
        const uint32_t sbase = sb + st * STAGE_B;
        const int k0 = c * BKc;
#pragma unroll
        for (int t = 0; t < 8; t++) {
            const int mat = t >> 1;
            const int rem = ((t & 1) << 8) + tid;
            const int row = rem >> 2, seg = rem & 3;
            const uint32_t dst = sbase + mat * MAT_B + row * (BKP * 2) + seg * 16;
            const __nv_bfloat16* src;
            if      (mat == 0) src = Ahi + (size_t)(m0 + row) * DM + k0 + seg * 8;
            else if (mat == 1) src = Alo + (size_t)(m0 + row) * DM + k0 + seg * 8;
            else if (mat == 2) src = Bhi + (size_t)(n0 + row) * DM + k0 + seg * 8;
            else               src = Blo + (size_t)(n0 + row) * DM + k0 + seg * 8;
            cp16(dst, src);
        }
        asm volatile("cp.async.commit_group;");
    };

    load_stage(0, 0);

    for (int c = 0; c < NKCH; c++) {
        if (c + 1 < NKCH) {
            load_stage(c + 1, (c + 1) & 1);
            asm volatile("cp.async.wait_group 1;" ::: "memory");
        } else {
            asm volatile("cp.async.wait_group 0;" ::: "memory");
        }
        __syncthreads();

        const uint32_t sbase = sb + (c & 1) * STAGE_B;
        const uint32_t aHi = sbase;
        const uint32_t aLo = sbase + MAT_B;
        const uint32_t bHi = sbase + 2 * MAT_B;
        const uint32_t bLo = sbase + 3 * MAT_B;

        const int arow = warp_m * 64 + (lane & 15);
        const int aseg = (lane >> 4) * 8;
        const int bn   = warp_n * 32 + ((lane >> 4) * 8) + (lane & 7);
        const int bk   = ((lane >> 3) & 1) * 8;

#pragma unroll
        for (int ks = 0; ks < 2; ks++) {
            const int k0 = ks * 16;
            uint32_t ah[4][4], al[4][4];
#pragma unroll
            for (int mt = 0; mt < 4; mt++) {
                uint32_t off = ((arow + mt * 16) * BKP + k0 + aseg) * 2;
                ldsm4(ah[mt], aHi + off);
                ldsm4(al[mt], aLo + off);
            }
            uint32_t bh[2][4], bl[2][4];
#pragma unroll
            for (int np = 0; np < 2; np++) {
                uint32_t off = ((bn + np * 16) * BKP + k0 + bk) * 2;
                ldsm4(bh[np], bHi + off);
                ldsm4(bl[np], bLo + off);
            }
#pragma unroll
            for (int mt = 0; mt < 4; mt++)
#pragma unroll
                for (int nt = 0; nt < 4; nt++) {
                    const uint32_t* Bh = &bh[nt >> 1][(nt & 1) * 2];
                    const uint32_t* Bl = &bl[nt >> 1][(nt & 1) * 2];
                    mma16816(acc[mt][nt], ah[mt], Bh);
                    mma16816(acc[mt][nt], ah[mt], Bl);
                    mma16816(acc[mt][nt], al[mt], Bh);
                }
        }
        __syncthreads();
    }

    const int rbase = m0 + warp_m * 64 + (lane >> 2);
    const int cbase = n0 + warp_n * 32 + (lane & 3) * 2;
#pragma unroll
    for (int mt = 0; mt < 4; mt++) {
#pragma unroll
        for (int nt = 0; nt < 4; nt++) {
            const int col = cbase + nt * 8;
            const float b0 = bias[col], b1 = bias[col + 1];
            const size_t a0 = (size_t)(rbase + mt * 16) * DM + col;
            const size_t a1 = (size_t)(rbase + mt * 16 + 8) * DM + col;
            if (OUTMODE == 0) {
                OutF[a0]     = acc[mt][nt][0] + b0;
                OutF[a0 + 1] = acc[mt][nt][1] + b1;
                OutF[a1]     = acc[mt][nt][2] + b0;
                OutF[a1 + 1] = acc[mt][nt][3] + b1;
            } else {
                float v0 = (acc[mt][nt][0] + b0) * scale;
                float v1 = (acc[mt][nt][1] + b1) * scale;
                float v2 = (acc[mt][nt][2] + b0) * scale;
                float v3 = (acc[mt][nt][3] + b1) * scale;
                uint32_t h01, l01, h23, l23;
                split_pair(v0, v1, h01, l01);
                split_pair(v2, v3, h23, l23);
                *(uint32_t*)(Ohi + a0) = h01;
                *(uint32_t*)(Olo + a0) = l01;
                *(uint32_t*)(Ohi + a1) = h23;
                *(uint32_t*)(Olo + a1) = l23;
            }
        }
    }
}

__global__ __launch_bounds__(256, 1) void qkv_mma_kernel(
    const float* __restrict__ bq, const float* __restrict__ bk, const float* __restrict__ bv)
{
    const size_t wo = (size_t)blockIdx.z * DM * DM;
    const float* bias = (blockIdx.z == 0) ? bq : (blockIdx.z == 1) ? bk : bv;
    __nv_bfloat16* Ohi = (blockIdx.z == 0) ? g_qhi : (blockIdx.z == 1) ? g_khi : g_vhi;
    __nv_bfloat16* Olo = (blockIdx.z == 0) ? g_qlo : (blockIdx.z == 1) ? g_klo : g_vlo;
    const float scale = (blockIdx.z == 0) ? 0.125f : 1.0f;   // 1/sqrt(64), exact
    gemm_mma_body<1>(g_xhi, g_xlo, g_whi + wo, g_wlo + wo, bias, nullptr, Ohi, Olo, scale);
}

__global__ __launch_bounds__(256, 1) void oproj_mma_kernel(const float* __restrict__ bo,
                                                           float* __restrict__ Out)
{
    const size_t wo = (size_t)3 * DM * DM;
    gemm_mma_body<0>(g_ahi, g_alo, g_whi + wo, g_wlo + wo, bo, Out, nullptr, nullptr, 1.0f);
}

// ---------------- tensor-core flash attention ----------------
// CTA: 128 q rows x (b,h). 8 warps, warp w owns rows 16w..16w+15.
// K-blocks of 64. S via 3-term hi/lo mma; online softmax; PV via 3-term
// (Phi*Vhi + Phi*Vlo + Plo*Vhi), V frags via ldmatrix.trans.
#define LQ 72
#define QTILE_B (128 * LQ * 2)     // 18432
#define KVTILE_B (64 * LQ * 2)     // 9216
#define STAGE_KV (4 * KVTILE_B)    // 36864
#define SM_QHI 0
#define SM_QLO QTILE_B
#define SM_KV0 (2 * QTILE_B)
#define ATTN_SMEM (2 * QTILE_B + 2 * STAGE_KV)   // 110592

__global__ __launch_bounds__(256, 1) void attn_kernel()
{
    extern __shared__ char smc[];
    const uint32_t sb = smem_u32(smc);
    const int qt = blockIdx.x, bh = blockIdx.y;
    const int b = bh >> 4, h = bh & 15;
    const int tid = threadIdx.x, w = tid >> 5, lane = tid & 31;
    const int q0 = qt * 128;
    const size_t tok0 = (size_t)b * TT;
    const int hoff = h * DK;

    // Q tile (hi+lo), loaded once
#pragma unroll
    for (int it = 0; it < 4; it++) {
        int idx = tid + it * 256;
        int row = idx >> 3, seg = idx & 7;
        size_t g = (tok0 + q0 + row) * DM + hoff + seg * 8;
        uint32_t so = (uint32_t)(row * LQ + seg * 8) * 2;
        cp16(sb + SM_QHI + so, g_qhi + g);
        cp16(sb + SM_QLO + so, g_qlo + g);
    }
    asm volatile("cp.async.commit_group;");

    auto load_kv = [&](int jb, int st) {
        const uint32_t sbase = sb + SM_KV0 + st * STAGE_KV;
#pragma unroll
        for (int it = 0; it < 2; it++) {
            int idx = tid + it * 256;
            int row = idx >> 3, seg = idx & 7;
            size_t g = (tok0 + jb * 64 + row) * DM + hoff + seg * 8;
            uint32_t so = (uint32_t)(row * LQ + seg * 8) * 2;
            cp16(sbase + so,                g_khi + g);
            cp16(sbase + KVTILE_B + so,     g_klo + g);
            cp16(sbase + 2 * KVTILE_B + so, g_vhi + g);
            cp16(sbase + 3 * KVTILE_B + so, g_vlo + g);
        }
        asm volatile("cp.async.commit_group;");
    };

    const int nkb = 2 * qt + 2;
    load_kv(0, 0);

    uint32_t qfh[4][4], qfl[4][4];
    float of[8][4];
#pragma unroll
    for (int i = 0; i < 8; i++)
#pragma unroll
        for (int j = 0; j < 4; j++) of[i][j] = 0.f;
    float mi0 = -INFINITY, mi1 = -INFINITY, li0 = 0.f, li1 = 0.f;

    for (int jb = 0; jb < nkb; jb++) {
        if (jb + 1 < nkb) {
            load_kv(jb + 1, (jb + 1) & 1);
            asm volatile("cp.async.wait_group 1;" ::: "memory");
        } else {
            asm volatile("cp.async.wait_group 0;" ::: "memory");
        }
        __syncthreads();

        if (jb == 0) {
#pragma unroll
            for (int ks = 0; ks < 4; ks++) {
                uint32_t off = (uint32_t)((16 * w + (lane & 15)) * LQ + ks * 16 + (lane >> 4) * 8) * 2;
                ldsm4(qfh[ks], sb + SM_QHI + off);
                ldsm4(qfl[ks], sb + SM_QLO + off);
            }
        }

        const bool active = (jb * 64 <= q0 + 16 * w + 15);
        if (active) {
            const uint32_t kbase = sb + SM_KV0 + (jb & 1) * STAGE_KV;
            float sf[8][4];
#pragma unroll
            for (int i = 0; i < 8; i++)
#pragma unroll
                for (int j = 0; j < 4; j++) sf[i][j] = 0.f;

            // S = Q K^T (3-term)
#pragma unroll
            for (int ks = 0; ks < 4; ks++) {
                uint32_t kh[4][4], kl[4][4];
#pragma unroll
                for (int np = 0; np < 4; np++) {
                    uint32_t off = (uint32_t)((np * 16 + (lane >> 4) * 8 + (lane & 7)) * LQ
                                              + ks * 16 + ((lane >> 3) & 1) * 8) * 2;
                    ldsm4(kh[np], kbase + off);
                    ldsm4(kl[np], kbase + KVTILE_B + off);
                }
#pragma unroll
                for (int nt = 0; nt < 8; nt++) {
                    const uint32_t* Bh = &kh[nt >> 1][(nt & 1) * 2];
                    const uint32_t* Bl = &kl[nt >> 1][(nt & 1) * 2];
                    mma16816(sf[nt], qfh[ks], Bh);
                    mma16816(sf[nt], qfh[ks], Bl);
                    mma16816(sf[nt], qfl[ks], Bh);
                }
            }

            // causal mask
            const int r0 = q0 + 16 * w + (lane >> 2), r1 = r0 + 8;
            if (jb * 64 + 63 > r0) {
#pragma unroll
                for (int nt = 0; nt < 8; nt++) {
                    int gk = jb * 64 + nt * 8 + (lane & 3) * 2;
                    if (gk     > r0) sf[nt][0] = -INFINITY;
                    if (gk + 1 > r0) sf[nt][1] = -INFINITY;
                    if (gk     > r1) sf[nt][2] = -INFINITY;
                    if (gk + 1 > r1) sf[nt][3] = -INFINITY;
                }
            }

            // online softmax (rows r0, r1); quad lanes share a row
            float mx0 = -INFINITY, mx1 = -INFINITY;
#pragma unroll
            for (int nt = 0; nt < 8; nt++) {
                mx0 = fmaxf(mx0, fmaxf(sf[nt][0], sf[nt][1]));
                mx1 = fmaxf(mx1, fmaxf(sf[nt][2], sf[nt][3]));
            }
            mx0 = fmaxf(mx0, __shfl_xor_sync(0xffffffffu, mx0, 1));
            mx0 = fmaxf(mx0, __shfl_xor_sync(0xffffffffu, mx0, 2));
            mx1 = fmaxf(mx1, __shfl_xor_sync(0xffffffffu, mx1, 1));
            mx1 = fmaxf(mx1, __shfl_xor_sync(0xffffffffu, mx1, 2));
            const float mn0 = fmaxf(mi0, mx0), mn1 = fmaxf(mi1, mx1);
            const float c0 = __expf(mi0 - mn0), c1 = __expf(mi1 - mn1);
            float rs0 = 0.f, rs1 = 0.f;
#pragma unroll
            for (int nt = 0; nt < 8; nt++) {
                sf[nt][0] = __expf(sf[nt][0] - mn0);
                sf[nt][1] = __expf(sf[nt][1] - mn0);
                sf[nt][2] = __expf(sf[nt][2] - mn1);
                sf[nt][3] = __expf(sf[nt][3] - mn1);
                rs0 += sf[nt][0] + sf[nt][1];
                rs1 += sf[nt][2] + sf[nt][3];
            }
            rs0 += __shfl_xor_sync(0xffffffffu, rs0, 1);
            rs0 += __shfl_xor_sync(0xffffffffu, rs0, 2);
            rs1 += __shfl_xor_sync(0xffffffffu, rs1, 1);
            rs1 += __shfl_xor_sync(0xffffffffu, rs1, 2);
            li0 = li0 * c0 + rs0; li1 = li1 * c1 + rs1;
            mi0 = mn0; mi1 = mn1;
#pragma unroll
            for (int nt = 0; nt < 8; nt++) {
                of[nt][0] *= c0; of[nt][1] *= c0;
                of[nt][2] *= c1; of[nt][3] *= c1;
            }

            // O += P V (3-term), V^T frags via ldmatrix.trans
            const uint32_t vbase = kbase + 2 * KVTILE_B;
#pragma unroll
            for (int ks = 0; ks < 4; ks++) {
                uint32_t ph[4], pl[4];
                split_pair(sf[2 * ks][0],     sf[2 * ks][1],     ph[0], pl[0]);
                split_pair(sf[2 * ks][2],     sf[2 * ks][3],     ph[1], pl[1]);
                split_pair(sf[2 * ks + 1][0], sf[2 * ks + 1][1], ph[2], pl[2]);
                split_pair(sf[2 * ks + 1][2], sf[2 * ks + 1][3], ph[3], pl[3]);
                uint32_t vh[4][4], vl[4][4];
#pragma unroll
                for (int np = 0; np < 4; np++) {
                    uint32_t off = (uint32_t)((ks * 16 + ((lane >> 3) & 1) * 8 + (lane & 7)) * LQ
                                              + np * 16 + (lane >> 4) * 8) * 2;
                    ldsm4t(vh[np], vbase + off);
                    ldsm4t(vl[np], vbase + KVTILE_B + off);
                }
#pragma unroll
                for (int nt = 0; nt < 8; nt++) {
                    const uint32_t* Bh = &vh[nt >> 1][(nt & 1) * 2];
                    const uint32_t* Bl = &vl[nt >> 1][(nt & 1) * 2];
                    mma16816(of[nt], ph, Bh);
                    mma16816(of[nt], ph, Bl);
                    mma16816(of[nt], pl, Bh);
                }
            }
        }
        __syncthreads();
    }

    // epilogue: normalize, write hi/lo bf16
    const float inv0 = 1.f / li0, inv1 = 1.f / li1;
    const int trow = q0 + 16 * w + (lane >> 2);
#pragma unroll
    for (int nt = 0; nt < 8; nt++) {
        const int col = hoff + nt * 8 + (lane & 3) * 2;
        float v0 = of[nt][0] * inv0, v1 = of[nt][1] * inv0;
        float v2 = of[nt][2] * inv1, v3 = of[nt][3] * inv1;
        uint32_t h01, l01, h23, l23;
        split_pair(v0, v1, h01, l01);
        split_pair(v2, v3, h23, l23);
        const size_t a0 = (tok0 + trow) * DM + col;
        const size_t a1 = (tok0 + trow + 8) * DM + col;
        *(uint32_t*)(g_ahi + a0) = h01;
        *(uint32_t*)(g_alo + a0) = l01;
        *(uint32_t*)(g_ahi + a1) = h23;
        *(uint32_t*)(g_alo + a1) = l23;
    }
}

// ----------------------------------------------------------------------------
extern "C" void kernel_launch(void* const* d_in, const int* in_sizes, int n_in,
                              void* d_out, int out_size)
{
    const float* q  = (const float*)d_in[0];
    const float* Wq = (const float*)d_in[2];
    const float* bq = (const float*)d_in[3];
    const float* Wk = (const float*)d_in[4];
    const float* bk = (const float*)d_in[5];
    const float* Wv = (const float*)d_in[6];
    const float* bv = (const float*)d_in[7];
    const float* Wo = (const float*)d_in[8];
    const float* bo = (const float*)d_in[9];
    float* out = (float*)d_out;

    cudaFuncSetAttribute(qkv_mma_kernel, cudaFuncAttributeMaxDynamicSharedMemorySize, GEMM_SMEM);
    cudaFuncSetAttribute(oproj_mma_kernel, cudaFuncAttributeMaxDynamicSharedMemorySize, GEMM_SMEM);
    cudaFuncSetAttribute(attn_kernel, cudaFuncAttributeMaxDynamicSharedMemorySize, ATTN_SMEM);

    __nv_bfloat16 *whi, *wlo, *xhi, *xlo;
    cudaGetSymbolAddress((void**)&whi, g_whi);
    cudaGetSymbolAddress((void**)&wlo, g_wlo);
    cudaGetSymbolAddress((void**)&xhi, g_xhi);
    cudaGetSymbolAddress((void**)&xlo, g_xlo);

    const int nX4 = MT * DM / 4, nW4 = DM * DM / 4;
    cvt_kernel<<<(nX4 + 255) / 256, 256>>>(q, xhi, xlo, nX4);
    cvt_kernel<<<(nW4 + 255) / 256, 256>>>(Wq, whi, wlo, nW4);
    cvt_kernel<<<(nW4 + 255) / 256, 256>>>(Wk, whi + (size_t)DM * DM, wlo + (size_t)DM * DM, nW4);
    cvt_kernel<<<(nW4 + 255) / 256, 256>>>(Wv, whi + (size_t)2 * DM * DM, wlo + (size_t)2 * DM * DM, nW4);
    cvt_kernel<<<(nW4 + 255) / 256, 256>>>(Wo, whi + (size_t)3 * DM * DM, wlo + (size_t)3 * DM * DM, nW4);

    dim3 gq(DM / 128, MT / 128, 3);
    qkv_mma_kernel<<<gq, 256, GEMM_SMEM>>>(bq, bk, bv);

    dim3 ga(TT / 128, BB * NH);
    attn_kernel<<<ga, 256, ATTN_SMEM>>>();

    dim3 go(DM / 128, MT / 128, 1);
    oproj_mma_kernel<<<go, 256, GEMM_SMEM>>>(bo, out);
}

// round 6
// speedup vs baseline: 3.4709x; 1.3631x over previous
#include <cuda_runtime.h>
#include <cuda_fp16.h>
#include <math.h>
#include <stdint.h>

#define DM 1024
#define NH 16
#define DK 64
#define BB 4
#define TT 2048
#define MT (BB*TT)   // 8192 rows

// ---------------- scratch (static; allocation forbidden) ----------------
__device__ __half g_xhi[(size_t)MT * DM];
__device__ __half g_xlo[(size_t)MT * DM];
__device__ __half g_qhi[(size_t)MT * DM];
__device__ __half g_qlo[(size_t)MT * DM];
__device__ __half g_khi[(size_t)MT * DM];
__device__ __half g_vhi[(size_t)MT * DM];
__device__ __half g_vlo[(size_t)MT * DM];
__device__ __half g_ahi[(size_t)MT * DM];
__device__ __half g_alo[(size_t)MT * DM];
__device__ __half g_whi[(size_t)4 * DM * DM];

// ---------------- helpers ----------------
__device__ __forceinline__ uint32_t smem_u32(const void* p) {
    uint32_t a;
    asm("{ .reg .u64 t; cvta.to.shared.u64 t, %1; cvt.u32.u64 %0, t; }" : "=r"(a) : "l"(p));
    return a;
}
__device__ __forceinline__ void cp16(uint32_t dst, const void* src) {
    asm volatile("cp.async.cg.shared.global [%0], [%1], 16;" :: "r"(dst), "l"(src));
}
__device__ __forceinline__ void ldsm4(uint32_t* r, uint32_t addr) {
    asm volatile("ldmatrix.sync.aligned.m8n8.x4.shared.b16 {%0,%1,%2,%3}, [%4];"
                 : "=r"(r[0]), "=r"(r[1]), "=r"(r[2]), "=r"(r[3]) : "r"(addr));
}
__device__ __forceinline__ void ldsm4t(uint32_t* r, uint32_t addr) {
    asm volatile("ldmatrix.sync.aligned.m8n8.x4.trans.shared.b16 {%0,%1,%2,%3}, [%4];"
                 : "=r"(r[0]), "=r"(r[1]), "=r"(r[2]), "=r"(r[3]) : "r"(addr));
}
__device__ __forceinline__ void mma16816(float* c, const uint32_t* a, const uint32_t* b) {
    asm volatile("mma.sync.aligned.m16n8k16.row.col.f32.f16.f16.f32 "
                 "{%0,%1,%2,%3}, {%4,%5,%6,%7}, {%8,%9}, {%0,%1,%2,%3};"
                 : "+f"(c[0]), "+f"(c[1]), "+f"(c[2]), "+f"(c[3])
                 : "r"(a[0]), "r"(a[1]), "r"(a[2]), "r"(a[3]), "r"(b[0]), "r"(b[1]));
}
__device__ __forceinline__ uint32_t packh2(float x, float y) {
    __half2 t = __floats2half2_rn(x, y);   // low = x
    return *(uint32_t*)&t;
}
__device__ __forceinline__ void split_pair(float x, float y, uint32_t& hi, uint32_t& lo) {
    hi = packh2(x, y);
    __half2 hv = *(__half2*)&hi;
    lo = packh2(x - __low2float(hv), y - __high2float(hv));
}

// ---------------- fp32 -> fp16 converters ----------------
__global__ __launch_bounds__(256) void cvt2_kernel(const float* __restrict__ x,
                                                   __half* __restrict__ hi,
                                                   __half* __restrict__ lo, int n4)
{
    int i = blockIdx.x * 256 + threadIdx.x;
    if (i >= n4) return;
    float4 v = ((const float4*)x)[i];
    uint32_t h0, l0, h1, l1;
    split_pair(v.x, v.y, h0, l0);
    split_pair(v.z, v.w, h1, l1);
    uint32_t* hp = (uint32_t*)(hi + (size_t)i * 4);
    uint32_t* lp = (uint32_t*)(lo + (size_t)i * 4);
    hp[0] = h0; hp[1] = h1;
    lp[0] = l0; lp[1] = l1;
}

__global__ __launch_bounds__(256) void cvt1_kernel(const float* __restrict__ x,
                                                   __half* __restrict__ hi, int n4)
{
    int i = blockIdx.x * 256 + threadIdx.x;
    if (i >= n4) return;
    float4 v = ((const float4*)x)[i];
    uint32_t* hp = (uint32_t*)(hi + (size_t)i * 4);
    hp[0] = packh2(v.x, v.y);
    hp[1] = packh2(v.z, v.w);
}

// ---------------- mma.sync GEMM: Out[M,N] = A[M,K] @ W[N,K]^T + bias ----------------
// A = hi+lo fp16, W = hi fp16. acc += Ahi*Whi + Alo*Whi.
#define BKc 32
#define BKP 40
#define MAT_B (128 * BKP * 2)      // 10240
#define STAGE_B (3 * MAT_B)        // Ahi, Alo, Bhi
#define GEMM_SMEM (2 * STAGE_B)    // 61440
#define NKCH (DM / BKc)            // 32

// OUTMODE 0: fp32 out. OUTMODE 1: fp16 hi(/lo) out, scaled; Olo may be null.
template<int OUTMODE>
__device__ __forceinline__ void gemm_mma_body(
    const __half* __restrict__ Ahi, const __half* __restrict__ Alo,
    const __half* __restrict__ Bhi,
    const float* __restrict__ bias, float* __restrict__ OutF,
    __half* __restrict__ Ohi, __half* __restrict__ Olo, float scale)
{
    extern __shared__ char smc[];
    const uint32_t sb = smem_u32(smc);
    const int tid = threadIdx.x, wid = tid >> 5, lane = tid & 31;
    const int warp_m = wid >> 2, warp_n = wid & 3;
    const int m0 = blockIdx.y * 128, n0 = blockIdx.x * 128;

    float acc[4][4][4];
#pragma unroll
    for (int i = 0; i < 4; i++)
#pragma unroll
        for (int j = 0; j < 4; j++)
#pragma unroll
            for (int k = 0; k < 4; k++) acc[i][j][k] = 0.f;

    auto load_stage = [&](int c, int st) {
        const uint32_t sbase = sb + st * STAGE_B;
        const int k0 = c * BKc;
#pragma unroll
        for (int t = 0; t < 6; t++) {
            const int mat = t >> 1;
            const int rem = ((t & 1) << 8) + tid;
            const int row = rem >> 2, seg = rem & 3;
            const uint32_t dst = sbase + mat * MAT_B + row * (BKP * 2) + seg * 16;
            const __half* src;
            if      (mat == 0) src = Ahi + (size_t)(m0 + row) * DM + k0 + seg * 8;
            else if (mat == 1) src = Alo + (size_t)(m0 + row) * DM + k0 + seg * 8;
            else               src = Bhi + (size_t)(n0 + row) * DM + k0 + seg * 8;
            cp16(dst, src);
        }
        asm volatile("cp.async.commit_group;");
    };

    load_stage(0, 0);

    for (int c = 0; c < NKCH; c++) {
        if (c + 1 < NKCH) {
            load_stage(c + 1, (c + 1) & 1);
            asm volatile("cp.async.wait_group 1;" ::: "memory");
        } else {
            asm volatile("cp.async.wait_group 0;" ::: "memory");
        }
        __syncthreads();

        const uint32_t sbase = sb + (c & 1) * STAGE_B;
        const uint32_t aHi = sbase;
        const uint32_t aLo = sbase + MAT_B;
        const uint32_t bHi = sbase + 2 * MAT_B;

        const int arow = warp_m * 64 + (lane & 15);
        const int aseg = (lane >> 4) * 8;
        const int bn   = warp_n * 32 + ((lane >> 4) * 8) + (lane & 7);
        const int bk   = ((lane >> 3) & 1) * 8;

#pragma unroll
        for (int ks = 0; ks < 2; ks++) {
            const int k0 = ks * 16;
            uint32_t ah[4][4], al[4][4];
#pragma unroll
            for (int mt = 0; mt < 4; mt++) {
                uint32_t off = ((arow + mt * 16) * BKP + k0 + aseg) * 2;
                ldsm4(ah[mt], aHi + off);
                ldsm4(al[mt], aLo + off);
            }
            uint32_t bh[2][4];
#pragma unroll
            for (int np = 0; np < 2; np++) {
                uint32_t off = ((bn + np * 16) * BKP + k0 + bk) * 2;
                ldsm4(bh[np], bHi + off);
            }
#pragma unroll
            for (int mt = 0; mt < 4; mt++)
#pragma unroll
                for (int nt = 0; nt < 4; nt++) {
                    const uint32_t* Bh = &bh[nt >> 1][(nt & 1) * 2];
                    mma16816(acc[mt][nt], ah[mt], Bh);
                    mma16816(acc[mt][nt], al[mt], Bh);
                }
        }
        __syncthreads();
    }

    const int rbase = m0 + warp_m * 64 + (lane >> 2);
    const int cbase = n0 + warp_n * 32 + (lane & 3) * 2;
#pragma unroll
    for (int mt = 0; mt < 4; mt++) {
#pragma unroll
        for (int nt = 0; nt < 4; nt++) {
            const int col = cbase + nt * 8;
            const float b0 = bias[col], b1 = bias[col + 1];
            const size_t a0 = (size_t)(rbase + mt * 16) * DM + col;
            const size_t a1 = (size_t)(rbase + mt * 16 + 8) * DM + col;
            if (OUTMODE == 0) {
                OutF[a0]     = acc[mt][nt][0] + b0;
                OutF[a0 + 1] = acc[mt][nt][1] + b1;
                OutF[a1]     = acc[mt][nt][2] + b0;
                OutF[a1 + 1] = acc[mt][nt][3] + b1;
            } else {
                float v0 = (acc[mt][nt][0] + b0) * scale;
                float v1 = (acc[mt][nt][1] + b1) * scale;
                float v2 = (acc[mt][nt][2] + b0) * scale;
                float v3 = (acc[mt][nt][3] + b1) * scale;
                if (Olo) {
                    uint32_t h01, l01, h23, l23;
                    split_pair(v0, v1, h01, l01);
                    split_pair(v2, v3, h23, l23);
                    *(uint32_t*)(Ohi + a0) = h01;
                    *(uint32_t*)(Olo + a0) = l01;
                    *(uint32_t*)(Ohi + a1) = h23;
                    *(uint32_t*)(Olo + a1) = l23;
                } else {
                    *(uint32_t*)(Ohi + a0) = packh2(v0, v1);
                    *(uint32_t*)(Ohi + a1) = packh2(v2, v3);
                }
            }
        }
    }
}

__global__ __launch_bounds__(256, 1) void qkv_mma_kernel(
    const float* __restrict__ bq, const float* __restrict__ bk, const float* __restrict__ bv)
{
    const size_t wo = (size_t)blockIdx.z * DM * DM;
    const float* bias = (blockIdx.z == 0) ? bq : (blockIdx.z == 1) ? bk : bv;
    __half* Ohi = (blockIdx.z == 0) ? g_qhi : (blockIdx.z == 1) ? g_khi : g_vhi;
    __half* Olo = (blockIdx.z == 0) ? g_qlo : (blockIdx.z == 1) ? nullptr : g_vlo;
    const float scale = (blockIdx.z == 0) ? 0.125f : 1.0f;   // 1/sqrt(64), exact
    gemm_mma_body<1>(g_xhi, g_xlo, g_whi + wo, bias, nullptr, Ohi, Olo, scale);
}

__global__ __launch_bounds__(256, 1) void oproj_mma_kernel(const float* __restrict__ bo,
                                                           float* __restrict__ Out)
{
    const size_t wo = (size_t)3 * DM * DM;
    gemm_mma_body<0>(g_ahi, g_alo, g_whi + wo, bo, Out, nullptr, nullptr, 1.0f);
}

// ---------------- tensor-core flash attention ----------------
// CTA: 128 q rows x (b,h). 8 warps; K-blocks of 64.
// S = Qhi*Khi + Qlo*Khi (K quantized); PV = Phi*Vhi + Phi*Vlo (P quantized).
#define LQ 72
#define QTILE_B (128 * LQ * 2)     // 18432
#define KVTILE_B (64 * LQ * 2)     // 9216
#define STAGE_KV (3 * KVTILE_B)    // Khi, Vhi, Vlo
#define SM_QHI 0
#define SM_QLO QTILE_B
#define SM_KV0 (2 * QTILE_B)
#define ATTN_SMEM (2 * QTILE_B + 2 * STAGE_KV)   // 92160

__global__ __launch_bounds__(256, 1) void attn_kernel()
{
    extern __shared__ char smc[];
    const uint32_t sb = smem_u32(smc);
    const int qt = blockIdx.x, bh = blockIdx.y;
    const int b = bh >> 4, h = bh & 15;
    const int tid = threadIdx.x, w = tid >> 5, lane = tid & 31;
    const int q0 = qt * 128;
    const size_t tok0 = (size_t)b * TT;
    const int hoff = h * DK;

    // Q tile (hi+lo), loaded once
#pragma unroll
    for (int it = 0; it < 4; it++) {
        int idx = tid + it * 256;
        int row = idx >> 3, seg = idx & 7;
        size_t g = (tok0 + q0 + row) * DM + hoff + seg * 8;
        uint32_t so = (uint32_t)(row * LQ + seg * 8) * 2;
        cp16(sb + SM_QHI + so, g_qhi + g);
        cp16(sb + SM_QLO + so, g_qlo + g);
    }
    asm volatile("cp.async.commit_group;");

    auto load_kv = [&](int jb, int st) {
        const uint32_t sbase = sb + SM_KV0 + st * STAGE_KV;
#pragma unroll
        for (int it = 0; it < 2; it++) {
            int idx = tid + it * 256;
            int row = idx >> 3, seg = idx & 7;
            size_t g = (tok0 + jb * 64 + row) * DM + hoff + seg * 8;
            uint32_t so = (uint32_t)(row * LQ + seg * 8) * 2;
            cp16(sbase + so,                g_khi + g);
            cp16(sbase + KVTILE_B + so,     g_vhi + g);
            cp16(sbase + 2 * KVTILE_B + so, g_vlo + g);
        }
        asm volatile("cp.async.commit_group;");
    };

    const int nkb = 2 * qt + 2;
    load_kv(0, 0);

    uint32_t qfh[4][4], qfl[4][4];
    float of[8][4];
#pragma unroll
    for (int i = 0; i < 8; i++)
#pragma unroll
        for (int j = 0; j < 4; j++) of[i][j] = 0.f;
    float mi0 = -INFINITY, mi1 = -INFINITY, li0 = 0.f, li1 = 0.f;

    for (int jb = 0; jb < nkb; jb++) {
        if (jb + 1 < nkb) {
            load_kv(jb + 1, (jb + 1) & 1);
            asm volatile("cp.async.wait_group 1;" ::: "memory");
        } else {
            asm volatile("cp.async.wait_group 0;" ::: "memory");
        }
        __syncthreads();

        if (jb == 0) {
#pragma unroll
            for (int ks = 0; ks < 4; ks++) {
                uint32_t off = (uint32_t)((16 * w + (lane & 15)) * LQ + ks * 16 + (lane >> 4) * 8) * 2;
                ldsm4(qfh[ks], sb + SM_QHI + off);
                ldsm4(qfl[ks], sb + SM_QLO + off);
            }
        }

        const bool active = (jb * 64 <= q0 + 16 * w + 15);
        if (active) {
            const uint32_t kbase = sb + SM_KV0 + (jb & 1) * STAGE_KV;
            float sf[8][4];
#pragma unroll
            for (int i = 0; i < 8; i++)
#pragma unroll
                for (int j = 0; j < 4; j++) sf[i][j] = 0.f;

            // S = Q K^T (2-term: Qhi*Khi + Qlo*Khi)
#pragma unroll
            for (int ks = 0; ks < 4; ks++) {
                uint32_t kh[4][4];
#pragma unroll
                for (int np = 0; np < 4; np++) {
                    uint32_t off = (uint32_t)((np * 16 + (lane >> 4) * 8 + (lane & 7)) * LQ
                                              + ks * 16 + ((lane >> 3) & 1) * 8) * 2;
                    ldsm4(kh[np], kbase + off);
                }
#pragma unroll
                for (int nt = 0; nt < 8; nt++) {
                    const uint32_t* Bh = &kh[nt >> 1][(nt & 1) * 2];
                    mma16816(sf[nt], qfh[ks], Bh);
                    mma16816(sf[nt], qfl[ks], Bh);
                }
            }

            // causal mask
            const int r0 = q0 + 16 * w + (lane >> 2), r1 = r0 + 8;
            if (jb * 64 + 63 > r0) {
#pragma unroll
                for (int nt = 0; nt < 8; nt++) {
                    int gk = jb * 64 + nt * 8 + (lane & 3) * 2;
                    if (gk     > r0) sf[nt][0] = -INFINITY;
                    if (gk + 1 > r0) sf[nt][1] = -INFINITY;
                    if (gk     > r1) sf[nt][2] = -INFINITY;
                    if (gk + 1 > r1) sf[nt][3] = -INFINITY;
                }
            }

            // online softmax (rows r0, r1)
            float mx0 = -INFINITY, mx1 = -INFINITY;
#pragma unroll
            for (int nt = 0; nt < 8; nt++) {
                mx0 = fmaxf(mx0, fmaxf(sf[nt][0], sf[nt][1]));
                mx1 = fmaxf(mx1, fmaxf(sf[nt][2], sf[nt][3]));
            }
            mx0 = fmaxf(mx0, __shfl_xor_sync(0xffffffffu, mx0, 1));
            mx0 = fmaxf(mx0, __shfl_xor_sync(0xffffffffu, mx0, 2));
            mx1 = fmaxf(mx1, __shfl_xor_sync(0xffffffffu, mx1, 1));
            mx1 = fmaxf(mx1, __shfl_xor_sync(0xffffffffu, mx1, 2));
            const float mn0 = fmaxf(mi0, mx0), mn1 = fmaxf(mi1, mx1);
            const float c0 = __expf(mi0 - mn0), c1 = __expf(mi1 - mn1);
            float rs0 = 0.f, rs1 = 0.f;
#pragma unroll
            for (int nt = 0; nt < 8; nt++) {
                sf[nt][0] = __expf(sf[nt][0] - mn0);
                sf[nt][1] = __expf(sf[nt][1] - mn0);
                sf[nt][2] = __expf(sf[nt][2] - mn1);
                sf[nt][3] = __expf(sf[nt][3] - mn1);
                rs0 += sf[nt][0] + sf[nt][1];
                rs1 += sf[nt][2] + sf[nt][3];
            }
            rs0 += __shfl_xor_sync(0xffffffffu, rs0, 1);
            rs0 += __shfl_xor_sync(0xffffffffu, rs0, 2);
            rs1 += __shfl_xor_sync(0xffffffffu, rs1, 1);
            rs1 += __shfl_xor_sync(0xffffffffu, rs1, 2);
            li0 = li0 * c0 + rs0; li1 = li1 * c1 + rs1;
            mi0 = mn0; mi1 = mn1;
#pragma unroll
            for (int nt = 0; nt < 8; nt++) {
                of[nt][0] *= c0; of[nt][1] *= c0;
                of[nt][2] *= c1; of[nt][3] *= c1;
            }

            // O += P V (2-term: Phi*Vhi + Phi*Vlo)
            const uint32_t vbase = kbase + KVTILE_B;
#pragma unroll
            for (int ks = 0; ks < 4; ks++) {
                uint32_t ph[4];
                ph[0] = packh2(sf[2 * ks][0],     sf[2 * ks][1]);
                ph[1] = packh2(sf[2 * ks][2],     sf[2 * ks][3]);
                ph[2] = packh2(sf[2 * ks + 1][0], sf[2 * ks + 1][1]);
                ph[3] = packh2(sf[2 * ks + 1][2], sf[2 * ks + 1][3]);
                uint32_t vh[4][4], vl[4][4];
#pragma unroll
                for (int np = 0; np < 4; np++) {
                    uint32_t off = (uint32_t)((ks * 16 + ((lane >> 3) & 1) * 8 + (lane & 7)) * LQ
                                              + np * 16 + (lane >> 4) * 8) * 2;
                    ldsm4t(vh[np], vbase + off);
                    ldsm4t(vl[np], vbase + KVTILE_B + off);
                }
#pragma unroll
                for (int nt = 0; nt < 8; nt++) {
                    const uint32_t* Bh = &vh[nt >> 1][(nt & 1) * 2];
                    const uint32_t* Bl = &vl[nt >> 1][(nt & 1) * 2];
                    mma16816(of[nt], ph, Bh);
                    mma16816(of[nt], ph, Bl);
                }
            }
        }
        __syncthreads();
    }

    // epilogue: normalize, write hi/lo fp16
    const float inv0 = 1.f / li0, inv1 = 1.f / li1;
    const int trow = q0 + 16 * w + (lane >> 2);
#pragma unroll
    for (int nt = 0; nt < 8; nt++) {
        const int col = hoff + nt * 8 + (lane & 3) * 2;
        float v0 = of[nt][0] * inv0, v1 = of[nt][1] * inv0;
        float v2 = of[nt][2] * inv1, v3 = of[nt][3] * inv1;
        uint32_t h01, l01, h23, l23;
        split_pair(v0, v1, h01, l01);
        split_pair(v2, v3, h23, l23);
        const size_t a0 = (tok0 + trow) * DM + col;
        const size_t a1 = (tok0 + trow + 8) * DM + col;
        *(uint32_t*)(g_ahi + a0) = h01;
        *(uint32_t*)(g_alo + a0) = l01;
        *(uint32_t*)(g_ahi + a1) = h23;
        *(uint32_t*)(g_alo + a1) = l23;
    }
}

// ----------------------------------------------------------------------------
extern "C" void kernel_launch(void* const* d_in, const int* in_sizes, int n_in,
                              void* d_out, int out_size)
{
    const float* q  = (const float*)d_in[0];
    const float* Wq = (const float*)d_in[2];
    const float* bq = (const float*)d_in[3];
    const float* Wk = (const float*)d_in[4];
    const float* bk = (const float*)d_in[5];
    const float* Wv = (const float*)d_in[6];
    const float* bv = (const float*)d_in[7];
    const float* Wo = (const float*)d_in[8];
    const float* bo = (const float*)d_in[9];
    float* out = (float*)d_out;

    cudaFuncSetAttribute(qkv_mma_kernel, cudaFuncAttributeMaxDynamicSharedMemorySize, GEMM_SMEM);
    cudaFuncSetAttribute(oproj_mma_kernel, cudaFuncAttributeMaxDynamicSharedMemorySize, GEMM_SMEM);
    cudaFuncSetAttribute(attn_kernel, cudaFuncAttributeMaxDynamicSharedMemorySize, ATTN_SMEM);

    __half *whi, *xhi, *xlo;
    cudaGetSymbolAddress((void**)&whi, g_whi);
    cudaGetSymbolAddress((void**)&xhi, g_xhi);
    cudaGetSymbolAddress((void**)&xlo, g_xlo);

    const int nX4 = MT * DM / 4, nW4 = DM * DM / 4;
    cvt2_kernel<<<(nX4 + 255) / 256, 256>>>(q, xhi, xlo, nX4);
    cvt1_kernel<<<(nW4 + 255) / 256, 256>>>(Wq, whi, nW4);
    cvt1_kernel<<<(nW4 + 255) / 256, 256>>>(Wk, whi + (size_t)DM * DM, nW4);
    cvt1_kernel<<<(nW4 + 255) / 256, 256>>>(Wv, whi + (size_t)2 * DM * DM, nW4);
    cvt1_kernel<<<(nW4 + 255) / 256, 256>>>(Wo, whi + (size_t)3 * DM * DM, nW4);

    dim3 gq(DM / 128, MT / 128, 3);
    qkv_mma_kernel<<<gq, 256, GEMM_SMEM>>>(bq, bk, bv);

    dim3 ga(TT / 128, BB * NH);
    attn_kernel<<<ga, 256, ATTN_SMEM>>>();

    dim3 go(DM / 128, MT / 128, 1);
    oproj_mma_kernel<<<go, 256, GEMM_SMEM>>>(bo, out);
}

// round 7
// speedup vs baseline: 4.2757x; 1.2319x over previous
#include <cuda_runtime.h>
#include <cuda_fp16.h>
#include <math.h>
#include <stdint.h>

#define DM 1024
#define NH 16
#define DK 64
#define BB 4
#define TT 2048
#define MT (BB*TT)   // 8192 rows

// ---------------- scratch (static; allocation forbidden) ----------------
__device__ __half g_xhi[(size_t)MT * DM];
__device__ __half g_xlo[(size_t)MT * DM];
__device__ __half g_qhi[(size_t)MT * DM];
__device__ __half g_qlo[(size_t)MT * DM];
__device__ __half g_khi[(size_t)MT * DM];
__device__ __half g_vhi[(size_t)MT * DM];
__device__ __half g_vlo[(size_t)MT * DM];
__device__ __half g_ahi[(size_t)MT * DM];
__device__ __half g_alo[(size_t)MT * DM];
__device__ __half g_whi[(size_t)4 * DM * DM];

// ---------------- helpers ----------------
__device__ __forceinline__ uint32_t smem_u32(const void* p) {
    uint32_t a;
    asm("{ .reg .u64 t; cvta.to.shared.u64 t, %1; cvt.u32.u64 %0, t; }" : "=r"(a) : "l"(p));
    return a;
}
__device__ __forceinline__ void cp16(uint32_t dst, const void* src) {
    asm volatile("cp.async.cg.shared.global [%0], [%1], 16;" :: "r"(dst), "l"(src));
}
__device__ __forceinline__ void ldsm4(uint32_t* r, uint32_t addr) {
    asm volatile("ldmatrix.sync.aligned.m8n8.x4.shared.b16 {%0,%1,%2,%3}, [%4];"
                 : "=r"(r[0]), "=r"(r[1]), "=r"(r[2]), "=r"(r[3]) : "r"(addr));
}
__device__ __forceinline__ void ldsm4t(uint32_t* r, uint32_t addr) {
    asm volatile("ldmatrix.sync.aligned.m8n8.x4.trans.shared.b16 {%0,%1,%2,%3}, [%4];"
                 : "=r"(r[0]), "=r"(r[1]), "=r"(r[2]), "=r"(r[3]) : "r"(addr));
}
__device__ __forceinline__ void mma16816(float* c, const uint32_t* a, const uint32_t* b) {
    asm volatile("mma.sync.aligned.m16n8k16.row.col.f32.f16.f16.f32 "
                 "{%0,%1,%2,%3}, {%4,%5,%6,%7}, {%8,%9}, {%0,%1,%2,%3};"
                 : "+f"(c[0]), "+f"(c[1]), "+f"(c[2]), "+f"(c[3])
                 : "r"(a[0]), "r"(a[1]), "r"(a[2]), "r"(a[3]), "r"(b[0]), "r"(b[1]));
}
__device__ __forceinline__ uint32_t packh2(float x, float y) {
    __half2 t = __floats2half2_rn(x, y);   // low = x
    return *(uint32_t*)&t;
}
__device__ __forceinline__ void split_pair(float x, float y, uint32_t& hi, uint32_t& lo) {
    hi = packh2(x, y);
    __half2 hv = *(__half2*)&hi;
    lo = packh2(x - __low2float(hv), y - __high2float(hv));
}

// ---------------- fp32 -> fp16 converters ----------------
__global__ __launch_bounds__(256) void cvt2_kernel(const float* __restrict__ x,
                                                   __half* __restrict__ hi,
                                                   __half* __restrict__ lo, int n4)
{
    int i = blockIdx.x * 256 + threadIdx.x;
    if (i >= n4) return;
    float4 v = ((const float4*)x)[i];
    uint32_t h0, l0, h1, l1;
    split_pair(v.x, v.y, h0, l0);
    split_pair(v.z, v.w, h1, l1);
    uint32_t* hp = (uint32_t*)(hi + (size_t)i * 4);
    uint32_t* lp = (uint32_t*)(lo + (size_t)i * 4);
    hp[0] = h0; hp[1] = h1;
    lp[0] = l0; lp[1] = l1;
}

// converts all 4 weight matrices; z selects
__global__ __launch_bounds__(256) void cvtw_kernel(const float* __restrict__ w0,
                                                   const float* __restrict__ w1,
                                                   const float* __restrict__ w2,
                                                   const float* __restrict__ w3,
                                                   __half* __restrict__ hi, int n4)
{
    int i = blockIdx.x * 256 + threadIdx.x;
    if (i >= n4) return;
    const float* src = (blockIdx.z == 0) ? w0 : (blockIdx.z == 1) ? w1 :
                       (blockIdx.z == 2) ? w2 : w3;
    float4 v = ((const float4*)src)[i];
    uint32_t* hp = (uint32_t*)(hi + (size_t)blockIdx.z * DM * DM + (size_t)i * 4);
    hp[0] = packh2(v.x, v.y);
    hp[1] = packh2(v.z, v.w);
}

// ---------------- mma.sync GEMM: Out[M,N] = A[M,K] @ W[N,K]^T + bias ----------------
// CTA 128x128, 4 warps (2x2), warp tile 64x64. BK=32, 3-stage cp.async,
// one __syncthreads per chunk. acc += Ahi*Whi + Alo*Whi.
#define BKc 32
#define BKP 40
#define MAT_B (128 * BKP * 2)      // 10240
#define STAGE_B (3 * MAT_B)        // Ahi, Alo, Bhi = 30720
#define NSTAGE 3
#define GEMM_SMEM (NSTAGE * STAGE_B)   // 92160
#define NKCH (DM / BKc)            // 32

// OUTMODE 0: fp32 out. OUTMODE 1: fp16 hi(/lo) out, scaled; Olo may be null.
template<int OUTMODE>
__device__ __forceinline__ void gemm_mma_body(
    const __half* __restrict__ Ahi, const __half* __restrict__ Alo,
    const __half* __restrict__ Bhi,
    const float* __restrict__ bias, float* __restrict__ OutF,
    __half* __restrict__ Ohi, __half* __restrict__ Olo, float scale)
{
    extern __shared__ char smc[];
    const uint32_t sb = smem_u32(smc);
    const int tid = threadIdx.x, wid = tid >> 5, lane = tid & 31;
    const int warp_m = wid & 1, warp_n = wid >> 1;       // 2 x 2
    const int m0 = blockIdx.y * 128, n0 = blockIdx.x * 128;

    float acc[4][8][4];
#pragma unroll
    for (int i = 0; i < 4; i++)
#pragma unroll
        for (int j = 0; j < 8; j++)
#pragma unroll
            for (int k = 0; k < 4; k++) acc[i][j][k] = 0.f;

    // stage loader: 3 mats x 128 rows x 4 segs = 1536 cp16, 12 per thread
    auto load_stage = [&](int c, int st) {
        const uint32_t sbase = sb + st * STAGE_B;
        const int k0 = c * BKc;
#pragma unroll
        for (int t = 0; t < 12; t++) {
            const int idx = t * 128 + tid;
            const int mat = idx >> 9;
            const int rem = idx & 511;
            const int row = rem >> 2, seg = rem & 3;
            const uint32_t dst = sbase + mat * MAT_B + row * (BKP * 2) + seg * 16;
            const __half* src;
            if      (mat == 0) src = Ahi + (size_t)(m0 + row) * DM + k0 + seg * 8;
            else if (mat == 1) src = Alo + (size_t)(m0 + row) * DM + k0 + seg * 8;
            else               src = Bhi + (size_t)(n0 + row) * DM + k0 + seg * 8;
            cp16(dst, src);
        }
        asm volatile("cp.async.commit_group;");
    };

    load_stage(0, 0);
    load_stage(1, 1);

    const int arow = warp_m * 64 + (lane & 15);
    const int aseg = (lane >> 4) * 8;
    const int bn   = warp_n * 64 + ((lane >> 4) * 8) + (lane & 7);
    const int bk   = ((lane >> 3) & 1) * 8;

    for (int c = 0; c < NKCH; c++) {
        // wait for stage c data (pending: c and possibly c+1)
        if (c + 1 < NKCH) { asm volatile("cp.async.wait_group 1;" ::: "memory"); }
        else              { asm volatile("cp.async.wait_group 0;" ::: "memory"); }
        __syncthreads();   // data visible to all; all warps done with stage c-1

        if (c + 2 < NKCH) load_stage(c + 2, (c + 2) % NSTAGE);

        const uint32_t sbase = sb + (c % NSTAGE) * STAGE_B;
        const uint32_t aHi = sbase;
        const uint32_t aLo = sbase + MAT_B;
        const uint32_t bHi = sbase + 2 * MAT_B;

#pragma unroll
        for (int ks = 0; ks < 2; ks++) {
            const int k0 = ks * 16;
            uint32_t ah[4][4], al[4][4];
#pragma unroll
            for (int mt = 0; mt < 4; mt++) {
                uint32_t off = ((arow + mt * 16) * BKP + k0 + aseg) * 2;
                ldsm4(ah[mt], aHi + off);
                ldsm4(al[mt], aLo + off);
            }
            uint32_t bh[4][4];
#pragma unroll
            for (int np = 0; np < 4; np++) {
                uint32_t off = ((bn + np * 16) * BKP + k0 + bk) * 2;
                ldsm4(bh[np], bHi + off);
            }
#pragma unroll
            for (int mt = 0; mt < 4; mt++)
#pragma unroll
                for (int nt = 0; nt < 8; nt++) {
                    const uint32_t* Bh = &bh[nt >> 1][(nt & 1) * 2];
                    mma16816(acc[mt][nt], ah[mt], Bh);
                    mma16816(acc[mt][nt], al[mt], Bh);
                }
        }
    }

    const int rbase = m0 + warp_m * 64 + (lane >> 2);
    const int cbase = n0 + warp_n * 64 + (lane & 3) * 2;
#pragma unroll
    for (int mt = 0; mt < 4; mt++) {
#pragma unroll
        for (int nt = 0; nt < 8; nt++) {
            const int col = cbase + nt * 8;
            const float b0 = bias[col], b1 = bias[col + 1];
            const size_t a0 = (size_t)(rbase + mt * 16) * DM + col;
            const size_t a1 = (size_t)(rbase + mt * 16 + 8) * DM + col;
            if (OUTMODE == 0) {
                OutF[a0]     = acc[mt][nt][0] + b0;
                OutF[a0 + 1] = acc[mt][nt][1] + b1;
                OutF[a1]     = acc[mt][nt][2] + b0;
                OutF[a1 + 1] = acc[mt][nt][3] + b1;
            } else {
                float v0 = (acc[mt][nt][0] + b0) * scale;
                float v1 = (acc[mt][nt][1] + b1) * scale;
                float v2 = (acc[mt][nt][2] + b0) * scale;
                float v3 = (acc[mt][nt][3] + b1) * scale;
                if (Olo) {
                    uint32_t h01, l01, h23, l23;
                    split_pair(v0, v1, h01, l01);
                    split_pair(v2, v3, h23, l23);
                    *(uint32_t*)(Ohi + a0) = h01;
                    *(uint32_t*)(Olo + a0) = l01;
                    *(uint32_t*)(Ohi + a1) = h23;
                    *(uint32_t*)(Olo + a1) = l23;
                } else {
                    *(uint32_t*)(Ohi + a0) = packh2(v0, v1);
                    *(uint32_t*)(Ohi + a1) = packh2(v2, v3);
                }
            }
        }
    }
}

__global__ __launch_bounds__(128, 2) void qkv_mma_kernel(
    const float* __restrict__ bq, const float* __restrict__ bk, const float* __restrict__ bv)
{
    const size_t wo = (size_t)blockIdx.z * DM * DM;
    const float* bias = (blockIdx.z == 0) ? bq : (blockIdx.z == 1) ? bk : bv;
    __half* Ohi = (blockIdx.z == 0) ? g_qhi : (blockIdx.z == 1) ? g_khi : g_vhi;
    __half* Olo = (blockIdx.z == 0) ? g_qlo : (blockIdx.z == 1) ? nullptr : g_vlo;
    const float scale = (blockIdx.z == 0) ? 0.125f : 1.0f;   // 1/sqrt(64), exact
    gemm_mma_body<1>(g_xhi, g_xlo, g_whi + wo, bias, nullptr, Ohi, Olo, scale);
}

__global__ __launch_bounds__(128, 2) void oproj_mma_kernel(const float* __restrict__ bo,
                                                           float* __restrict__ Out)
{
    const size_t wo = (size_t)3 * DM * DM;
    gemm_mma_body<0>(g_ahi, g_alo, g_whi + wo, bo, Out, nullptr, nullptr, 1.0f);
}

// ---------------- tensor-core flash attention (unchanged from R6) ----------------
#define LQ 72
#define QTILE_B (128 * LQ * 2)     // 18432
#define KVTILE_B (64 * LQ * 2)     // 9216
#define STAGE_KV (3 * KVTILE_B)    // Khi, Vhi, Vlo
#define SM_QHI 0
#define SM_QLO QTILE_B
#define SM_KV0 (2 * QTILE_B)
#define ATTN_SMEM (2 * QTILE_B + 2 * STAGE_KV)   // 92160

__global__ __launch_bounds__(256, 1) void attn_kernel()
{
    extern __shared__ char smc[];
    const uint32_t sb = smem_u32(smc);
    const int qt = blockIdx.x, bh = blockIdx.y;
    const int b = bh >> 4, h = bh & 15;
    const int tid = threadIdx.x, w = tid >> 5, lane = tid & 31;
    const int q0 = qt * 128;
    const size_t tok0 = (size_t)b * TT;
    const int hoff = h * DK;

#pragma unroll
    for (int it = 0; it < 4; it++) {
        int idx = tid + it * 256;
        int row = idx >> 3, seg = idx & 7;
        size_t g = (tok0 + q0 + row) * DM + hoff + seg * 8;
        uint32_t so = (uint32_t)(row * LQ + seg * 8) * 2;
        cp16(sb + SM_QHI + so, g_qhi + g);
        cp16(sb + SM_QLO + so, g_qlo + g);
    }
    asm volatile("cp.async.commit_group;");

    auto load_kv = [&](int jb, int st) {
        const uint32_t sbase = sb + SM_KV0 + st * STAGE_KV;
#pragma unroll
        for (int it = 0; it < 2; it++) {
            int idx = tid + it * 256;
            int row = idx >> 3, seg = idx & 7;
            size_t g = (tok0 + jb * 64 + row) * DM + hoff + seg * 8;
            uint32_t so = (uint32_t)(row * LQ + seg * 8) * 2;
            cp16(sbase + so,                g_khi + g);
            cp16(sbase + KVTILE_B + so,     g_vhi + g);
            cp16(sbase + 2 * KVTILE_B + so, g_vlo + g);
        }
        asm volatile("cp.async.commit_group;");
    };

    const int nkb = 2 * qt + 2;
    load_kv(0, 0);

    uint32_t qfh[4][4], qfl[4][4];
    float of[8][4];
#pragma unroll
    for (int i = 0; i < 8; i++)
#pragma unroll
        for (int j = 0; j < 4; j++) of[i][j] = 0.f;
    float mi0 = -INFINITY, mi1 = -INFINITY, li0 = 0.f, li1 = 0.f;

    for (int jb = 0; jb < nkb; jb++) {
        if (jb + 1 < nkb) {
            load_kv(jb + 1, (jb + 1) & 1);
            asm volatile("cp.async.wait_group 1;" ::: "memory");
        } else {
            asm volatile("cp.async.wait_group 0;" ::: "memory");
        }
        __syncthreads();

        if (jb == 0) {
#pragma unroll
            for (int ks = 0; ks < 4; ks++) {
                uint32_t off = (uint32_t)((16 * w + (lane & 15)) * LQ + ks * 16 + (lane >> 4) * 8) * 2;
                ldsm4(qfh[ks], sb + SM_QHI + off);
                ldsm4(qfl[ks], sb + SM_QLO + off);
            }
        }

        const bool active = (jb * 64 <= q0 + 16 * w + 15);
        if (active) {
            const uint32_t kbase = sb + SM_KV0 + (jb & 1) * STAGE_KV;
            float sf[8][4];
#pragma unroll
            for (int i = 0; i < 8; i++)
#pragma unroll
                for (int j = 0; j < 4; j++) sf[i][j] = 0.f;

#pragma unroll
            for (int ks = 0; ks < 4; ks++) {
                uint32_t kh[4][4];
#pragma unroll
                for (int np = 0; np < 4; np++) {
                    uint32_t off = (uint32_t)((np * 16 + (lane >> 4) * 8 + (lane & 7)) * LQ
                                              + ks * 16 + ((lane >> 3) & 1) * 8) * 2;
                    ldsm4(kh[np], kbase + off);
                }
#pragma unroll
                for (int nt = 0; nt < 8; nt++) {
                    const uint32_t* Bh = &kh[nt >> 1][(nt & 1) * 2];
                    mma16816(sf[nt], qfh[ks], Bh);
                    mma16816(sf[nt], qfl[ks], Bh);
                }
            }

            const int r0 = q0 + 16 * w + (lane >> 2), r1 = r0 + 8;
            if (jb * 64 + 63 > r0) {
#pragma unroll
                for (int nt = 0; nt < 8; nt++) {
                    int gk = jb * 64 + nt * 8 + (lane & 3) * 2;
                    if (gk     > r0) sf[nt][0] = -INFINITY;
                    if (gk + 1 > r0) sf[nt][1] = -INFINITY;
                    if (gk     > r1) sf[nt][2] = -INFINITY;
                    if (gk + 1 > r1) sf[nt][3] = -INFINITY;
                }
            }

            float mx0 = -INFINITY, mx1 = -INFINITY;
#pragma unroll
            for (int nt = 0; nt < 8; nt++) {
                mx0 = fmaxf(mx0, fmaxf(sf[nt][0], sf[nt][1]));
                mx1 = fmaxf(mx1, fmaxf(sf[nt][2], sf[nt][3]));
            }
            mx0 = fmaxf(mx0, __shfl_xor_sync(0xffffffffu, mx0, 1));
            mx0 = fmaxf(mx0, __shfl_xor_sync(0xffffffffu, mx0, 2));
            mx1 = fmaxf(mx1, __shfl_xor_sync(0xffffffffu, mx1, 1));
            mx1 = fmaxf(mx1, __shfl_xor_sync(0xffffffffu, mx1, 2));
            const float mn0 = fmaxf(mi0, mx0), mn1 = fmaxf(mi1, mx1);
            const float c0 = __expf(mi0 - mn0), c1 = __expf(mi1 - mn1);
            float rs0 = 0.f, rs1 = 0.f;
#pragma unroll
            for (int nt = 0; nt < 8; nt++) {
                sf[nt][0] = __expf(sf[nt][0] - mn0);
                sf[nt][1] = __expf(sf[nt][1] - mn0);
                sf[nt][2] = __expf(sf[nt][2] - mn1);
                sf[nt][3] = __expf(sf[nt][3] - mn1);
                rs0 += sf[nt][0] + sf[nt][1];
                rs1 += sf[nt][2] + sf[nt][3];
            }
            rs0 += __shfl_xor_sync(0xffffffffu, rs0, 1);
            rs0 += __shfl_xor_sync(0xffffffffu, rs0, 2);
            rs1 += __shfl_xor_sync(0xffffffffu, rs1, 1);
            rs1 += __shfl_xor_sync(0xffffffffu, rs1, 2);
            li0 = li0 * c0 + rs0; li1 = li1 * c1 + rs1;
            mi0 = mn0; mi1 = mn1;
#pragma unroll
            for (int nt = 0; nt < 8; nt++) {
                of[nt][0] *= c0; of[nt][1] *= c0;
                of[nt][2] *= c1; of[nt][3] *= c1;
            }

            const uint32_t vbase = kbase + KVTILE_B;
#pragma unroll
            for (int ks = 0; ks < 4; ks++) {
                uint32_t ph[4];
                ph[0] = packh2(sf[2 * ks][0],     sf[2 * ks][1]);
                ph[1] = packh2(sf[2 * ks][2],     sf[2 * ks][3]);
                ph[2] = packh2(sf[2 * ks + 1][0], sf[2 * ks + 1][1]);
                ph[3] = packh2(sf[2 * ks + 1][2], sf[2 * ks + 1][3]);
                uint32_t vh[4][4], vl[4][4];
#pragma unroll
                for (int np = 0; np < 4; np++) {
                    uint32_t off = (uint32_t)((ks * 16 + ((lane >> 3) & 1) * 8 + (lane & 7)) * LQ
                                              + np * 16 + (lane >> 4) * 8) * 2;
                    ldsm4t(vh[np], vbase + off);
                    ldsm4t(vl[np], vbase + KVTILE_B + off);
                }
#pragma unroll
                for (int nt = 0; nt < 8; nt++) {
                    const uint32_t* Bh = &vh[nt >> 1][(nt & 1) * 2];
                    const uint32_t* Bl = &vl[nt >> 1][(nt & 1) * 2];
                    mma16816(of[nt], ph, Bh);
                    mma16816(of[nt], ph, Bl);
                }
            }
        }
        __syncthreads();
    }

    const float inv0 = 1.f / li0, inv1 = 1.f / li1;
    const int trow = q0 + 16 * w + (lane >> 2);
#pragma unroll
    for (int nt = 0; nt < 8; nt++) {
        const int col = hoff + nt * 8 + (lane & 3) * 2;
        float v0 = of[nt][0] * inv0, v1 = of[nt][1] * inv0;
        float v2 = of[nt][2] * inv1, v3 = of[nt][3] * inv1;
        uint32_t h01, l01, h23, l23;
        split_pair(v0, v1, h01, l01);
        split_pair(v2, v3, h23, l23);
        const size_t a0 = (tok0 + trow) * DM + col;
        const size_t a1 = (tok0 + trow + 8) * DM + col;
        *(uint32_t*)(g_ahi + a0) = h01;
        *(uint32_t*)(g_alo + a0) = l01;
        *(uint32_t*)(g_ahi + a1) = h23;
        *(uint32_t*)(g_alo + a1) = l23;
    }
}

// ----------------------------------------------------------------------------
extern "C" void kernel_launch(void* const* d_in, const int* in_sizes, int n_in,
                              void* d_out, int out_size)
{
    const float* q  = (const float*)d_in[0];
    const float* Wq = (const float*)d_in[2];
    const float* bq = (const float*)d_in[3];
    const float* Wk = (const float*)d_in[4];
    const float* bk = (const float*)d_in[5];
    const float* Wv = (const float*)d_in[6];
    const float* bv = (const float*)d_in[7];
    const float* Wo = (const float*)d_in[8];
    const float* bo = (const float*)d_in[9];
    float* out = (float*)d_out;

    cudaFuncSetAttribute(qkv_mma_kernel, cudaFuncAttributeMaxDynamicSharedMemorySize, GEMM_SMEM);
    cudaFuncSetAttribute(oproj_mma_kernel, cudaFuncAttributeMaxDynamicSharedMemorySize, GEMM_SMEM);
    cudaFuncSetAttribute(attn_kernel, cudaFuncAttributeMaxDynamicSharedMemorySize, ATTN_SMEM);

    __half *whi, *xhi, *xlo;
    cudaGetSymbolAddress((void**)&whi, g_whi);
    cudaGetSymbolAddress((void**)&xhi, g_xhi);
    cudaGetSymbolAddress((void**)&xlo, g_xlo);

    const int nX4 = MT * DM / 4, nW4 = DM * DM / 4;
    cvt2_kernel<<<(nX4 + 255) / 256, 256>>>(q, xhi, xlo, nX4);
    dim3 gw((nW4 + 255) / 256, 1, 4);
    cvtw_kernel<<<gw, 256>>>(Wq, Wk, Wv, Wo, whi, nW4);

    dim3 gq(DM / 128, MT / 128, 3);
    qkv_mma_kernel<<<gq, 128, GEMM_SMEM>>>(bq, bk, bv);

    dim3 ga(TT / 128, BB * NH);
    attn_kernel<<<ga, 256, ATTN_SMEM>>>();

    dim3 go(DM / 128, MT / 128, 1);
    oproj_mma_kernel<<<go, 128, GEMM_SMEM>>>(bo, out);
}